// round 12
// baseline (speedup 1.0000x reference)
#include <cuda_runtime.h>
#include <cuda_fp16.h>
#include <mma.h>
using namespace nvcuda;

#define NN 50000
#define NP 50048                 // padded to 64-row multiple
#define NE 1600000
#define HH 128
#define GG 256
#define BN_EPS 1e-5f
#define NB ((NN + 1023) / 1024)

// ---------------- scratch (static device memory) ----------------------------
__device__ int    g_is64;
__device__ int    g_deg[NN];
__device__ int    g_rowoff[NN + 1];
__device__ int    g_cursor[NN];
__device__ int2   g_edge[NE];
__device__ float  g_dinv[NN];
__device__ int    g_bsum[NB];
__device__ __half g_x16[NN * 8];
__device__ __half g_hA[NP * HH];      // ping
__device__ __half g_hB[NP * HH];      // pong
__device__ __half g_u16[NP * HH];     // agg staging
__device__ __half g_W16[2 * HH * HH];
__device__ float  g_Wp[64 * HH];

__device__ __forceinline__ int load_idx(const void* p, long long i, int is64) {
    if (is64) return (int)((const long long*)p)[i];
    return ((const int*)p)[i];
}
__device__ __forceinline__ int h2i(__half2 h) { return *reinterpret_cast<int*>(&h); }

// ---------------- prep: detect + x->fp16 + W->fp16 + deg=0 + pocket MLP -------
__global__ void k_prep(const float* __restrict__ x, const float* __restrict__ W,
                       const void* __restrict__ ei,
                       const float* __restrict__ pf,
                       const float* __restrict__ W1, const float* __restrict__ b1,
                       const float* __restrict__ W2, const float* __restrict__ b2,
                       const float* __restrict__ bilW) {
    int tid = threadIdx.x;
    if (blockIdx.x == gridDim.x - 1) {
        __shared__ float t1[64];
        __shared__ float spk[64];
        if (tid < 64) {
            float acc = b1[tid];
            for (int k = 0; k < 28; k++) acc += pf[k] * W1[k * 64 + tid];
            t1[tid] = fmaxf(acc, 0.f);
        }
        __syncthreads();
        if (tid < 64) {
            float acc = b2[tid];
            for (int jj = 0; jj < 64; jj++) acc += t1[jj] * W2[jj * 64 + tid];
            spk[tid] = acc;
        }
        __syncthreads();
        for (int idx = tid; idx < 64 * HH; idx += blockDim.x) {
            int o = idx / HH, i2 = idx % HH;
            const float4* wrow = (const float4*)(bilW + ((long long)o * HH + i2) * 64);
            float acc = 0.f;
            #pragma unroll
            for (int jj = 0; jj < 16; jj++) {
                float4 w = __ldg(&wrow[jj]);
                const float4 s = *(const float4*)&spk[jj * 4];
                acc += w.x * s.x + w.y * s.y + w.z * s.z + w.w * s.w;
            }
            g_Wp[o * HH + i2] = acc;
        }
        return;
    }
    if (blockIdx.x == 0 && tid < 32) {
        const int* p = (const int*)ei;
        int nz = 0;
        #pragma unroll
        for (int r = 0; r < 4; r++) if (p[(tid + r * 32) * 2 + 1] != 0) nz = 1;
        unsigned m = __ballot_sync(0xFFFFFFFFu, nz);
        if (tid == 0) g_is64 = (m == 0u) ? 1 : 0;
    }
    int v = blockIdx.x * blockDim.x + tid;
    if (v < NN) {
        g_deg[v] = 0;
        __half h[8];
        #pragma unroll
        for (int k = 0; k < 7; k++) h[k] = __float2half_rn(x[v * 7 + k]);
        h[7] = __float2half_rn(0.f);
        *(uint4*)&g_x16[v * 8] = *(uint4*)h;
    }
    if (v < 2 * HH * HH) g_W16[v] = __float2half_rn(W[v]);
}

// ---------------- CSR build ----------------------------------------------------
__global__ void k_deg_count(const void* ei) {
    int t = blockIdx.x * blockDim.x + threadIdx.x;
    if (t >= NE / 4) return;
    int d[4];
    if (g_is64) {
        int4 v0 = __ldg((const int4*)((const long long*)ei + NE) + t * 2);
        int4 v1 = __ldg((const int4*)((const long long*)ei + NE) + t * 2 + 1);
        d[0] = v0.x; d[1] = v0.z; d[2] = v1.x; d[3] = v1.z;
    } else {
        int4 v = __ldg((const int4*)((const int*)ei + NE) + t);
        d[0] = v.x; d[1] = v.y; d[2] = v.z; d[3] = v.w;
    }
    #pragma unroll
    for (int q = 0; q < 4; q++) atomicAdd(&g_deg[d[q]], 1);
}

__global__ void k_scanA() {
    int i = blockIdx.x * 1024 + threadIdx.x;
    int v = (i < NN) ? g_deg[i] : 0;
    int lane = threadIdx.x & 31, wid = threadIdx.x >> 5;
    int s = v;
    #pragma unroll
    for (int o = 1; o < 32; o <<= 1) {
        int t = __shfl_up_sync(0xFFFFFFFFu, s, o);
        if (lane >= o) s += t;
    }
    __shared__ int wsum[32];
    if (lane == 31) wsum[wid] = s;
    __syncthreads();
    if (wid == 0) {
        int t = wsum[lane];
        #pragma unroll
        for (int o = 1; o < 32; o <<= 1) {
            int u = __shfl_up_sync(0xFFFFFFFFu, t, o);
            if (lane >= o) t += u;
        }
        wsum[lane] = t;
    }
    __syncthreads();
    int incl = s + (wid > 0 ? wsum[wid - 1] : 0);
    if (i < NN) {
        g_rowoff[i] = incl - v;
        g_dinv[i]   = rsqrtf((float)v + 1.0f);
    }
    if (threadIdx.x == 1023) g_bsum[blockIdx.x] = incl;
}

// lookback scan-fixup + cursor init
__global__ void k_scanC() {
    __shared__ int soff;
    int b = blockIdx.x;
    if (threadIdx.x < 32) {
        int lane = threadIdx.x;
        int part = 0;
        for (int i = lane; i < b; i += 32) part += g_bsum[i];
        #pragma unroll
        for (int o = 16; o > 0; o >>= 1) part += __shfl_xor_sync(0xFFFFFFFFu, part, o);
        if (lane == 0) {
            soff = part;
            if (b == NB - 1) g_rowoff[NN] = part + g_bsum[NB - 1];
        }
    }
    __syncthreads();
    int i = b * 1024 + threadIdx.x;
    if (i < NN) {
        int v = g_rowoff[i] + soff;
        g_rowoff[i] = v;
        g_cursor[i] = v;
    }
}

__global__ void k_scatter(const void* ei) {
    int t = blockIdx.x * blockDim.x + threadIdx.x;
    if (t >= NE / 4) return;
    int s[4], d[4];
    if (g_is64) {
        int4 s0 = __ldg((const int4*)((const long long*)ei) + t * 2);
        int4 s1 = __ldg((const int4*)((const long long*)ei) + t * 2 + 1);
        int4 d0 = __ldg((const int4*)((const long long*)ei + NE) + t * 2);
        int4 d1 = __ldg((const int4*)((const long long*)ei + NE) + t * 2 + 1);
        s[0] = s0.x; s[1] = s0.z; s[2] = s1.x; s[3] = s1.z;
        d[0] = d0.x; d[1] = d0.z; d[2] = d1.x; d[3] = d1.z;
    } else {
        int4 sv = __ldg((const int4*)((const int*)ei) + t);
        int4 dv = __ldg((const int4*)((const int*)ei + NE) + t);
        s[0] = sv.x; s[1] = sv.y; s[2] = sv.z; s[3] = sv.w;
        d[0] = dv.x; d[1] = dv.y; d[2] = dv.z; d[3] = dv.w;
    }
    #pragma unroll
    for (int q = 0; q < 4; q++) {
        float c = g_dinv[s[q]] * g_dinv[d[q]];
        int pos = atomicAdd(&g_cursor[d[q]], 1);
        g_edge[pos] = make_int2(s[q], __float_as_int(c));
    }
}

// ---------------- fused layer-0: 7-dim agg (smem) + GEMM + BN + ReLU ----------
__global__ void __launch_bounds__(128) k_layer0(const float* __restrict__ W,
                                                const float* __restrict__ bias,
                                                const float* __restrict__ gamma,
                                                const float* __restrict__ beta,
                                                const float* __restrict__ mean,
                                                const float* __restrict__ var,
                                                __half* __restrict__ outp) {
    __shared__ float su[128][8];
    int row0 = blockIdx.x * 128;
    int tid = threadIdx.x;
    int v = row0 + tid;
    float acc[8] = {};
    if (v < NN) {
        float di = g_dinv[v];
        float c0 = di * di;
        uint4 u = *(const uint4*)&g_x16[v * 8];
        const __half2* hp = (const __half2*)&u;
        #pragma unroll
        for (int q = 0; q < 4; q++) {
            float2 f = __half22float2(hp[q]);
            acc[q * 2] = c0 * f.x; acc[q * 2 + 1] = c0 * f.y;
        }
        int e0 = g_rowoff[v], e1 = g_rowoff[v + 1];
        int e = e0;
        for (; e + 1 < e1; e += 2) {
            int2 eA = __ldg(&g_edge[e]);
            int2 eB = __ldg(&g_edge[e + 1]);
            uint4 uA = __ldg((const uint4*)&g_x16[(long long)eA.x * 8]);
            uint4 uB = __ldg((const uint4*)&g_x16[(long long)eB.x * 8]);
            float cA = __int_as_float(eA.y), cB = __int_as_float(eB.y);
            const __half2* ha = (const __half2*)&uA;
            const __half2* hb = (const __half2*)&uB;
            #pragma unroll
            for (int q = 0; q < 4; q++) {
                float2 fa = __half22float2(ha[q]);
                float2 fb = __half22float2(hb[q]);
                acc[q * 2]     += cA * fa.x + cB * fb.x;
                acc[q * 2 + 1] += cA * fa.y + cB * fb.y;
            }
        }
        for (; e < e1; e++) {
            int2 ed = __ldg(&g_edge[e]);
            uint4 u2 = __ldg((const uint4*)&g_x16[(long long)ed.x * 8]);
            float c = __int_as_float(ed.y);
            const __half2* hp2 = (const __half2*)&u2;
            #pragma unroll
            for (int q = 0; q < 4; q++) {
                float2 f = __half22float2(hp2[q]);
                acc[q * 2] += c * f.x; acc[q * 2 + 1] += c * f.y;
            }
        }
    }
    #pragma unroll
    for (int q = 0; q < 8; q++) su[tid][q] = acc[q];
    __syncthreads();
    float w[7];
    #pragma unroll
    for (int k = 0; k < 7; k++) w[k] = W[k * HH + tid];
    float rs = rsqrtf(var[tid] + BN_EPS);
    float scale = gamma[tid] * rs;
    float shift = (bias[tid] - mean[tid]) * scale + beta[tid];
    int rmax = min(128, NN - row0);
    for (int r = 0; r < rmax; r++) {
        float a = 0.f;
        #pragma unroll
        for (int k = 0; k < 7; k++) a += su[r][k] * w[k];
        outp[(long long)(row0 + r) * HH + tid] = __float2half_rn(fmaxf(a * scale + shift, 0.f));
    }
}

// ---------------- 128-dim aggregation (R7 shape: warp/node, 8x unroll) ---------
__global__ void k_agg(const __half* __restrict__ in16, __half* __restrict__ out16) {
    int v = (blockIdx.x * blockDim.x + threadIdx.x) >> 5;
    int lane = threadIdx.x & 31;
    if (v >= NN) return;
    float di = g_dinv[v];
    float c0 = di * di;
    int j = lane * 4;
    uint2 us = __ldg((const uint2*)(in16 + (long long)v * HH + j));
    float2 s0 = __half22float2(*(const __half2*)&us.x);
    float2 s1 = __half22float2(*(const __half2*)&us.y);
    float ax = c0 * s0.x, ay = c0 * s0.y, az = c0 * s1.x, aw = c0 * s1.y;
    int e0 = g_rowoff[v], e1 = g_rowoff[v + 1];
    int e = e0;
    for (; e + 7 < e1; e += 8) {
        int2 ed[8];
        uint2 u[8];
        #pragma unroll
        for (int q = 0; q < 8; q++) ed[q] = __ldg(&g_edge[e + q]);
        #pragma unroll
        for (int q = 0; q < 8; q++)
            u[q] = __ldg((const uint2*)(in16 + (long long)ed[q].x * HH + j));
        #pragma unroll
        for (int q = 0; q < 8; q++) {
            float c = __int_as_float(ed[q].y);
            float2 f0 = __half22float2(*(const __half2*)&u[q].x);
            float2 f1 = __half22float2(*(const __half2*)&u[q].y);
            ax += c * f0.x; ay += c * f0.y; az += c * f1.x; aw += c * f1.y;
        }
    }
    for (; e < e1; e++) {
        int2 ed = __ldg(&g_edge[e]);
        float c = __int_as_float(ed.y);
        uint2 u = __ldg((const uint2*)(in16 + (long long)ed.x * HH + j));
        float2 f0 = __half22float2(*(const __half2*)&u.x);
        float2 f1 = __half22float2(*(const __half2*)&u.y);
        ax += c * f0.x; ay += c * f0.y; az += c * f1.x; aw += c * f1.y;
    }
    uint2 o;
    *(__half2*)&o.x = __floats2half2_rn(ax, ay);
    *(__half2*)&o.y = __floats2half2_rn(az, aw);
    *(uint2*)(out16 + (long long)v * HH + j) = o;
}

// ---------------- tensor-core GEMM + fused BN/ReLU -----------------------------
__global__ void __launch_bounds__(128) k_gemm_tc(const __half* __restrict__ A16,
                                                 const __half* __restrict__ W16,
                                                 __half* __restrict__ C16,
                                                 const float* __restrict__ bias,
                                                 const float* __restrict__ gamma,
                                                 const float* __restrict__ beta,
                                                 const float* __restrict__ mean,
                                                 const float* __restrict__ var) {
    __shared__ float sC[4][16 * HH];
    __shared__ float s_sc[HH], s_sh[HH];
    int tid = threadIdx.x;
    int warp = tid >> 5, lane = tid & 31;
    {
        float rs = rsqrtf(var[tid] + BN_EPS);
        float sc = gamma[tid] * rs;
        s_sc[tid] = sc;
        s_sh[tid] = (bias[tid] - mean[tid]) * sc + beta[tid];
    }
    __syncthreads();

    int row0 = blockIdx.x * 64 + warp * 16;
    wmma::fragment<wmma::accumulator, 16, 16, 16, float> c_frag[8];
    #pragma unroll
    for (int n = 0; n < 8; n++) wmma::fill_fragment(c_frag[n], 0.0f);

    for (int k = 0; k < HH; k += 16) {
        wmma::fragment<wmma::matrix_a, 16, 16, 16, __half, wmma::row_major> a_frag;
        wmma::load_matrix_sync(a_frag, A16 + (long long)row0 * HH + k, HH);
        #pragma unroll
        for (int n = 0; n < 8; n++) {
            wmma::fragment<wmma::matrix_b, 16, 16, 16, __half, wmma::row_major> b_frag;
            wmma::load_matrix_sync(b_frag, W16 + k * HH + n * 16, HH);
            wmma::mma_sync(c_frag[n], a_frag, b_frag, c_frag[n]);
        }
    }
    float* myC = sC[warp];
    #pragma unroll
    for (int n = 0; n < 8; n++)
        wmma::store_matrix_sync(myC + n * 16, c_frag[n], HH, wmma::mem_row_major);
    __syncwarp();

    for (int gI = lane; gI < 16 * 16; gI += 32) {
        int r = gI >> 4, c8 = gI & 15;
        float o[8];
        #pragma unroll
        for (int q = 0; q < 8; q++) {
            int col = c8 * 8 + q;
            o[q] = fmaxf(myC[r * HH + col] * s_sc[col] + s_sh[col], 0.f);
        }
        __half2 h0 = __floats2half2_rn(o[0], o[1]);
        __half2 h1 = __floats2half2_rn(o[2], o[3]);
        __half2 h2 = __floats2half2_rn(o[4], o[5]);
        __half2 h3 = __floats2half2_rn(o[6], o[7]);
        int4 pk = make_int4(h2i(h0), h2i(h1), h2i(h2), h2i(h3));
        *(int4*)&C16[(long long)(row0 + r) * HH + c8 * 8] = pk;
    }
}

// ---------------- pool + bilinear + classifier ---------------------------------
__global__ void k_pool_final(const __half* __restrict__ hin,
                             const void* __restrict__ batch,
                             const float* __restrict__ bil_b,
                             const float* __restrict__ cW1, const float* __restrict__ cb1,
                             const float* __restrict__ cW2, const float* __restrict__ cb2,
                             float* __restrict__ out) {
    __shared__ int   sLo, sHi;
    __shared__ float lig[HH];
    __shared__ float part[HH];
    __shared__ float inter[64];
    __shared__ float c1[32];
    int g = blockIdx.x;
    int tid = threadIdx.x;   // 128
    int is64 = g_is64;
    if (tid < 2) {
        int key = g + tid;
        int lo = 0, hi = NN;
        while (lo < hi) {
            int mid = (lo + hi) >> 1;
            if (load_idx(batch, mid, is64) < key) lo = mid + 1; else hi = mid;
        }
        if (tid == 0) sLo = lo; else sHi = lo;
    }
    __syncthreads();
    int lo = sLo, hi = sHi;
    int n = hi - lo;
    int grp = tid >> 6;
    int ft = tid & 63;
    float s0 = 0.f, s1 = 0.f;
    for (int r = lo + grp; r < hi; r += 2) {
        uint u0 = __ldg((const uint*)(hin + (long long)r * HH + ft * 2));
        float2 f0 = __half22float2(*(const __half2*)&u0);
        s0 += f0.x; s1 += f0.y;
    }
    if (grp == 1) { part[ft * 2] = s0; part[ft * 2 + 1] = s1; }
    __syncthreads();
    if (grp == 0) {
        float cnt = fmaxf((float)n, 1.f);
        lig[ft * 2]     = (s0 + part[ft * 2]) / cnt;
        lig[ft * 2 + 1] = (s1 + part[ft * 2 + 1]) / cnt;
    }
    __syncthreads();
    if (tid < 64) {
        float acc = bil_b[tid];
        const float* wp = &g_Wp[tid * HH];
        #pragma unroll 8
        for (int i = 0; i < HH; i++) acc += lig[i] * wp[i];
        inter[tid] = acc;
    }
    __syncthreads();
    if (tid < 32) {
        float acc = cb1[tid];
        #pragma unroll 8
        for (int o = 0; o < 64; o++) acc += inter[o] * cW1[o * 32 + tid];
        c1[tid] = fmaxf(acc, 0.f);
    }
    __syncthreads();
    if (tid == 0) {
        float acc = cb2[0];
        #pragma unroll
        for (int t = 0; t < 32; t++) acc += c1[t] * cW2[t];
        out[g] = acc;
    }
}

// ---------------- launch ---------------------------------------------------------
extern "C" void kernel_launch(void* const* d_in, const int* in_sizes, int n_in,
                              void* d_out, int out_size) {
    const float* x       = (const float*)d_in[0];
    const void*  ei      = d_in[1];
    const void*  batch   = d_in[2];
    const float* pocket  = (const float*)d_in[3];
    const float* conv0_W = (const float*)d_in[4];
    const float* conv0_b = (const float*)d_in[5];
    const float* convs_W = (const float*)d_in[6];
    const float* convs_b = (const float*)d_in[7];
    const float* bn_g    = (const float*)d_in[8];
    const float* bn_b    = (const float*)d_in[9];
    const float* bn_m    = (const float*)d_in[10];
    const float* bn_v    = (const float*)d_in[11];
    const float* pW1     = (const float*)d_in[12];
    const float* pb1     = (const float*)d_in[13];
    const float* pW2     = (const float*)d_in[14];
    const float* pb2     = (const float*)d_in[15];
    const float* bilW    = (const float*)d_in[16];
    const float* bilb    = (const float*)d_in[17];
    const float* cW1     = (const float*)d_in[18];
    const float* cb1     = (const float*)d_in[19];
    const float* cW2     = (const float*)d_in[20];
    const float* cb2     = (const float*)d_in[21];
    float* out = (float*)d_out;

    __half* hA = nullptr; __half* hB = nullptr; __half* u16 = nullptr; __half* w16 = nullptr;
    cudaGetSymbolAddress((void**)&hA,  g_hA);
    cudaGetSymbolAddress((void**)&hB,  g_hB);
    cudaGetSymbolAddress((void**)&u16, g_u16);
    cudaGetSymbolAddress((void**)&w16, g_W16);

    const int TB = 256;
    int prep_blocks = (NN + TB - 1) / TB + 1;
    k_prep<<<prep_blocks, TB>>>(x, convs_W, ei, pocket, pW1, pb1, pW2, pb2, bilW);
    k_deg_count<<<(NE / 4 + TB - 1) / TB, TB>>>(ei);
    k_scanA<<<NB, 1024>>>();
    k_scanC<<<NB, 1024>>>();
    k_scatter<<<(NE / 4 + TB - 1) / TB, TB>>>(ei);

    int agg_blocks = (NN * 32 + TB - 1) / TB;

    // layer 0 -> A (fused small agg + gemm)
    k_layer0<<<(NN + 127) / 128, 128>>>(conv0_W, conv0_b, bn_g, bn_b, bn_m, bn_v, hA);
    // layer 1: agg(A)->U, gemm(U)->B
    k_agg<<<agg_blocks, TB>>>(hA, u16);
    k_gemm_tc<<<NP / 64, 128>>>(u16, w16, hB, convs_b,
                                bn_g + HH, bn_b + HH, bn_m + HH, bn_v + HH);
    // layer 2: agg(B)->U, gemm(U)->A
    k_agg<<<agg_blocks, TB>>>(hB, u16);
    k_gemm_tc<<<NP / 64, 128>>>(u16, w16 + HH * HH, hA, convs_b + HH,
                                bn_g + 2 * HH, bn_b + 2 * HH, bn_m + 2 * HH, bn_v + 2 * HH);

    // pool + bilinear + classifier (reads A)
    k_pool_final<<<GG, 128>>>(hA, batch, bilb, cW1, cb1, cW2, cb2, out);
}

// round 13
// speedup vs baseline: 1.5047x; 1.5047x over previous
#include <cuda_runtime.h>
#include <cuda_fp16.h>
#include <mma.h>
using namespace nvcuda;

#define NN 50000
#define NP 50048                 // padded to 64-row multiple
#define NE 1600000
#define HH 128
#define GG 256
#define BN_EPS 1e-5f
#define NB ((NN + 1023) / 1024)

// ---------------- scratch (static device memory) ----------------------------
__device__ int    g_is64;
__device__ int    g_deg[NN];
__device__ int    g_rowoff[NN + 1];
__device__ int    g_cursor[NN];
__device__ int2   g_edge[NE];
__device__ float  g_dinv[NN];
__device__ int    g_bsum[NB];
__device__ int    g_boff[NB];
__device__ __half g_x16[NN * 8];
__device__ __half g_u016[NN * 8];
__device__ __half g_u16[NP * HH];
__device__ __half g_h16[NP * HH];
__device__ __half g_W16[2 * HH * HH];
__device__ float  g_Wp[64 * HH];

__device__ __forceinline__ int load_idx(const void* p, long long i, int is64) {
    if (is64) return (int)((const long long*)p)[i];
    return ((const int*)p)[i];
}
__device__ __forceinline__ int h2i(__half2 h) { return *reinterpret_cast<int*>(&h); }

// ---------------- dtype detection -------------------------------------------
__global__ void k_detect(const void* ei) {
    const int* p = (const int*)ei;
    int lane = threadIdx.x;
    int nz = 0;
    #pragma unroll
    for (int r = 0; r < 4; r++) if (p[(lane + r * 32) * 2 + 1] != 0) nz = 1;
    unsigned m = __ballot_sync(0xFFFFFFFFu, nz);
    if (lane == 0) g_is64 = (m == 0u) ? 1 : 0;
}

// ---------------- CSR build: 4 edges per thread --------------------------------
__global__ void k_deg_count(const void* ei) {
    int t = blockIdx.x * blockDim.x + threadIdx.x;
    if (t >= NE / 4) return;
    int d[4];
    if (g_is64) {
        int4 v0 = __ldg((const int4*)((const long long*)ei + NE) + t * 2);
        int4 v1 = __ldg((const int4*)((const long long*)ei + NE) + t * 2 + 1);
        d[0] = v0.x; d[1] = v0.z; d[2] = v1.x; d[3] = v1.z;
    } else {
        int4 v = __ldg((const int4*)((const int*)ei + NE) + t);
        d[0] = v.x; d[1] = v.y; d[2] = v.z; d[3] = v.w;
    }
    #pragma unroll
    for (int q = 0; q < 4; q++) atomicAdd(&g_deg[d[q]], 1);
}

__global__ void k_scanA() {
    int i = blockIdx.x * 1024 + threadIdx.x;
    int v = (i < NN) ? g_deg[i] : 0;
    int lane = threadIdx.x & 31, wid = threadIdx.x >> 5;
    int s = v;
    #pragma unroll
    for (int o = 1; o < 32; o <<= 1) {
        int t = __shfl_up_sync(0xFFFFFFFFu, s, o);
        if (lane >= o) s += t;
    }
    __shared__ int wsum[32];
    if (lane == 31) wsum[wid] = s;
    __syncthreads();
    if (wid == 0) {
        int t = wsum[lane];
        #pragma unroll
        for (int o = 1; o < 32; o <<= 1) {
            int u = __shfl_up_sync(0xFFFFFFFFu, t, o);
            if (lane >= o) t += u;
        }
        wsum[lane] = t;
    }
    __syncthreads();
    int incl = s + (wid > 0 ? wsum[wid - 1] : 0);
    if (i < NN) {
        g_rowoff[i] = incl - v;
        g_dinv[i]   = rsqrtf((float)v + 1.0f);
    }
    if (threadIdx.x == 1023) g_bsum[blockIdx.x] = incl;
}

__global__ void k_scanB() {
    int lane = threadIdx.x;
    int carry = 0;
    for (int base = 0; base < NB; base += 32) {
        int idx = base + lane;
        int v = (idx < NB) ? g_bsum[idx] : 0;
        int s = v;
        #pragma unroll
        for (int o = 1; o < 32; o <<= 1) {
            int t = __shfl_up_sync(0xFFFFFFFFu, s, o);
            if (lane >= o) s += t;
        }
        if (idx < NB) g_boff[idx] = carry + s - v;
        carry += __shfl_sync(0xFFFFFFFFu, s, 31);
    }
    if (lane == 0) g_rowoff[NN] = carry;
}

__global__ void k_scanC() {
    int i = blockIdx.x * 1024 + threadIdx.x;
    if (i < NN) {
        int v = g_rowoff[i] + g_boff[blockIdx.x];
        g_rowoff[i] = v;
        g_cursor[i] = v;
    }
}

__global__ void k_scatter(const void* ei) {
    int t = blockIdx.x * blockDim.x + threadIdx.x;
    if (t >= NE / 4) return;
    int s[4], d[4];
    if (g_is64) {
        int4 s0 = __ldg((const int4*)((const long long*)ei) + t * 2);
        int4 s1 = __ldg((const int4*)((const long long*)ei) + t * 2 + 1);
        int4 d0 = __ldg((const int4*)((const long long*)ei + NE) + t * 2);
        int4 d1 = __ldg((const int4*)((const long long*)ei + NE) + t * 2 + 1);
        s[0] = s0.x; s[1] = s0.z; s[2] = s1.x; s[3] = s1.z;
        d[0] = d0.x; d[1] = d0.z; d[2] = d1.x; d[3] = d1.z;
    } else {
        int4 sv = __ldg((const int4*)((const int*)ei) + t);
        int4 dv = __ldg((const int4*)((const int*)ei + NE) + t);
        s[0] = sv.x; s[1] = sv.y; s[2] = sv.z; s[3] = sv.w;
        d[0] = dv.x; d[1] = dv.y; d[2] = dv.z; d[3] = dv.w;
    }
    #pragma unroll
    for (int q = 0; q < 4; q++) {
        float c = g_dinv[s[q]] * g_dinv[d[q]];
        int pos = atomicAdd(&g_cursor[d[q]], 1);
        g_edge[pos] = make_int2(s[q], __float_as_int(c));
    }
}

// ---------------- x -> fp16 padded [N,8]; W -> fp16 ---------------------------
__global__ void k_prep_x(const float* __restrict__ x) {
    int v = blockIdx.x * blockDim.x + threadIdx.x;
    if (v >= NN) return;
    __half h[8];
    #pragma unroll
    for (int k = 0; k < 7; k++) h[k] = __float2half_rn(x[v * 7 + k]);
    h[7] = __float2half_rn(0.f);
    *(uint4*)&g_x16[v * 8] = *(uint4*)h;
}

__global__ void k_w16(const float* __restrict__ W) {
    int i = blockIdx.x * blockDim.x + threadIdx.x;
    if (i < 2 * HH * HH) g_W16[i] = __float2half_rn(W[i]);
}

// ---------------- layer-0 aggregation in 7-dim space ---------------------------
__global__ void k_aggx() {
    int v = blockIdx.x * blockDim.x + threadIdx.x;
    if (v >= NN) return;
    float di = g_dinv[v];
    float c0 = di * di;
    float acc[8];
    {
        uint4 u = *(const uint4*)&g_x16[v * 8];
        const __half2* hp = (const __half2*)&u;
        #pragma unroll
        for (int q = 0; q < 4; q++) {
            float2 f = __half22float2(hp[q]);
            acc[q * 2] = c0 * f.x; acc[q * 2 + 1] = c0 * f.y;
        }
    }
    int e0 = g_rowoff[v], e1 = g_rowoff[v + 1];
    int e = e0;
    for (; e + 1 < e1; e += 2) {
        int2 eA = __ldg(&g_edge[e]);
        int2 eB = __ldg(&g_edge[e + 1]);
        uint4 uA = __ldg((const uint4*)&g_x16[(long long)eA.x * 8]);
        uint4 uB = __ldg((const uint4*)&g_x16[(long long)eB.x * 8]);
        float cA = __int_as_float(eA.y), cB = __int_as_float(eB.y);
        const __half2* ha = (const __half2*)&uA;
        const __half2* hb = (const __half2*)&uB;
        #pragma unroll
        for (int q = 0; q < 4; q++) {
            float2 fa = __half22float2(ha[q]);
            float2 fb = __half22float2(hb[q]);
            acc[q * 2]     += cA * fa.x + cB * fb.x;
            acc[q * 2 + 1] += cA * fa.y + cB * fb.y;
        }
    }
    for (; e < e1; e++) {
        int2 ed = __ldg(&g_edge[e]);
        uint4 u = __ldg((const uint4*)&g_x16[(long long)ed.x * 8]);
        float c = __int_as_float(ed.y);
        const __half2* hp = (const __half2*)&u;
        #pragma unroll
        for (int q = 0; q < 4; q++) {
            float2 f = __half22float2(hp[q]);
            acc[q * 2] += c * f.x; acc[q * 2 + 1] += c * f.y;
        }
    }
    __half2 o[4];
    #pragma unroll
    for (int q = 0; q < 4; q++) o[q] = __floats2half2_rn(acc[q * 2], acc[q * 2 + 1]);
    *(uint4*)&g_u016[v * 8] = *(uint4*)o;
}

// ---------------- layer-0 GEMM + BN + ReLU -------------------------------------
__global__ void k_gemm0(const float* __restrict__ W, const float* __restrict__ bias,
                        const float* __restrict__ gamma, const float* __restrict__ beta,
                        const float* __restrict__ mean,  const float* __restrict__ var) {
    __shared__ float su[32][8];
    int row0 = blockIdx.x * 32;
    int tid = threadIdx.x;
    if (tid < 32) {
        int gr = row0 + tid;
        uint4 u = (gr < NN) ? *(const uint4*)&g_u016[gr * 8]
                            : make_uint4(0, 0, 0, 0);
        const __half2* hp = (const __half2*)&u;
        #pragma unroll
        for (int q = 0; q < 4; q++) {
            float2 f = __half22float2(hp[q]);
            su[tid][q * 2] = f.x; su[tid][q * 2 + 1] = f.y;
        }
    }
    __syncthreads();
    float w[7];
    #pragma unroll
    for (int k = 0; k < 7; k++) w[k] = W[k * HH + tid];
    float rs = rsqrtf(var[tid] + BN_EPS);
    float scale = gamma[tid] * rs;
    float shift = (bias[tid] - mean[tid]) * scale + beta[tid];
    #pragma unroll 4
    for (int r = 0; r < 32; r++) {
        int gr = row0 + r;
        if (gr < NN) {
            float acc = 0.f;
            #pragma unroll
            for (int k = 0; k < 7; k++) acc += su[r][k] * w[k];
            g_h16[(long long)gr * HH + tid] = __float2half_rn(fmaxf(acc * scale + shift, 0.f));
        }
    }
}

// ---------------- 128-dim aggregation ------------------------------------------
__global__ void k_agg(const __half* __restrict__ in16, __half* __restrict__ out16) {
    int v = (blockIdx.x * blockDim.x + threadIdx.x) >> 5;
    int lane = threadIdx.x & 31;
    if (v >= NN) return;
    float di = g_dinv[v];
    float c0 = di * di;
    int j = lane * 4;
    uint2 us = __ldg((const uint2*)(in16 + (long long)v * HH + j));
    float2 s0 = __half22float2(*(const __half2*)&us.x);
    float2 s1 = __half22float2(*(const __half2*)&us.y);
    float ax = c0 * s0.x, ay = c0 * s0.y, az = c0 * s1.x, aw = c0 * s1.y;
    int e0 = g_rowoff[v], e1 = g_rowoff[v + 1];
    int e = e0;
    for (; e + 7 < e1; e += 8) {
        int2 ed[8];
        uint2 u[8];
        #pragma unroll
        for (int q = 0; q < 8; q++) ed[q] = __ldg(&g_edge[e + q]);
        #pragma unroll
        for (int q = 0; q < 8; q++)
            u[q] = __ldg((const uint2*)(in16 + (long long)ed[q].x * HH + j));
        #pragma unroll
        for (int q = 0; q < 8; q++) {
            float c = __int_as_float(ed[q].y);
            float2 f0 = __half22float2(*(const __half2*)&u[q].x);
            float2 f1 = __half22float2(*(const __half2*)&u[q].y);
            ax += c * f0.x; ay += c * f0.y; az += c * f1.x; aw += c * f1.y;
        }
    }
    for (; e < e1; e++) {
        int2 ed = __ldg(&g_edge[e]);
        float c = __int_as_float(ed.y);
        uint2 u = __ldg((const uint2*)(in16 + (long long)ed.x * HH + j));
        float2 f0 = __half22float2(*(const __half2*)&u.x);
        float2 f1 = __half22float2(*(const __half2*)&u.y);
        ax += c * f0.x; ay += c * f0.y; az += c * f1.x; aw += c * f1.y;
    }
    uint2 o;
    *(__half2*)&o.x = __floats2half2_rn(ax, ay);
    *(__half2*)&o.y = __floats2half2_rn(az, aw);
    *(uint2*)(out16 + (long long)v * HH + j) = o;
}

// ---------------- tensor-core GEMM + fused BN/ReLU -----------------------------
// 64 rows/block, 4 warps; warp = 16-row strip x 128 cols; fragments from gmem
__global__ void __launch_bounds__(128) k_gemm_tc(const __half* __restrict__ A16,
                                                 const __half* __restrict__ W16,
                                                 __half* __restrict__ C16,
                                                 const float* __restrict__ bias,
                                                 const float* __restrict__ gamma,
                                                 const float* __restrict__ beta,
                                                 const float* __restrict__ mean,
                                                 const float* __restrict__ var) {
    __shared__ float sC[4][16 * HH];     // 32 KB
    __shared__ float s_sc[HH], s_sh[HH];
    int tid = threadIdx.x;
    int warp = tid >> 5, lane = tid & 31;
    {
        float rs = rsqrtf(var[tid] + BN_EPS);
        float sc = gamma[tid] * rs;
        s_sc[tid] = sc;
        s_sh[tid] = (bias[tid] - mean[tid]) * sc + beta[tid];
    }
    __syncthreads();

    int row0 = blockIdx.x * 64 + warp * 16;   // always < NP (padded)
    wmma::fragment<wmma::accumulator, 16, 16, 16, float> c_frag[8];
    #pragma unroll
    for (int n = 0; n < 8; n++) wmma::fill_fragment(c_frag[n], 0.0f);

    for (int k = 0; k < HH; k += 16) {
        wmma::fragment<wmma::matrix_a, 16, 16, 16, __half, wmma::row_major> a_frag;
        wmma::load_matrix_sync(a_frag, A16 + (long long)row0 * HH + k, HH);
        #pragma unroll
        for (int n = 0; n < 8; n++) {
            wmma::fragment<wmma::matrix_b, 16, 16, 16, __half, wmma::row_major> b_frag;
            wmma::load_matrix_sync(b_frag, W16 + k * HH + n * 16, HH);
            wmma::mma_sync(c_frag[n], a_frag, b_frag, c_frag[n]);
        }
    }
    float* myC = sC[warp];
    #pragma unroll
    for (int n = 0; n < 8; n++)
        wmma::store_matrix_sync(myC + n * 16, c_frag[n], HH, wmma::mem_row_major);
    __syncwarp();

    // epilogue: 16 rows x 16 col-groups of 8
    for (int gI = lane; gI < 16 * 16; gI += 32) {
        int r = gI >> 4, c8 = gI & 15;
        float o[8];
        #pragma unroll
        for (int q = 0; q < 8; q++) {
            int col = c8 * 8 + q;
            o[q] = fmaxf(myC[r * HH + col] * s_sc[col] + s_sh[col], 0.f);
        }
        __half2 h0 = __floats2half2_rn(o[0], o[1]);
        __half2 h1 = __floats2half2_rn(o[2], o[3]);
        __half2 h2 = __floats2half2_rn(o[4], o[5]);
        __half2 h3 = __floats2half2_rn(o[6], o[7]);
        int4 pk = make_int4(h2i(h0), h2i(h1), h2i(h2), h2i(h3));
        *(int4*)&C16[(long long)(row0 + r) * HH + c8 * 8] = pk;
    }
}

// ---------------- pocket MLP + bilinear weight contraction ---------------------
__global__ void k_small(const float* __restrict__ pf,
                        const float* __restrict__ W1, const float* __restrict__ b1,
                        const float* __restrict__ W2, const float* __restrict__ b2,
                        const float* __restrict__ bilW) {
    __shared__ float t1[64];
    __shared__ float spk[64];
    int tid = threadIdx.x;
    if (tid < 64) {
        float acc = b1[tid];
        for (int k = 0; k < 28; k++) acc += pf[k] * W1[k * 64 + tid];
        t1[tid] = fmaxf(acc, 0.f);
    }
    __syncthreads();
    if (tid < 64) {
        float acc = b2[tid];
        for (int jj = 0; jj < 64; jj++) acc += t1[jj] * W2[jj * 64 + tid];
        spk[tid] = acc;
    }
    __syncthreads();
    for (int idx = tid; idx < 64 * HH; idx += blockDim.x) {
        int o = idx / HH, i2 = idx % HH;
        const float4* wrow = (const float4*)(bilW + ((long long)o * HH + i2) * 64);
        float acc = 0.f;
        #pragma unroll
        for (int jj = 0; jj < 16; jj++) {
            float4 w = __ldg(&wrow[jj]);
            const float4 s = *(const float4*)&spk[jj * 4];
            acc += w.x * s.x + w.y * s.y + w.z * s.z + w.w * s.w;
        }
        g_Wp[o * HH + i2] = acc;
    }
}

// ---------------- pool + bilinear + classifier ---------------------------------
__global__ void k_pool_final(const void* __restrict__ batch,
                             const float* __restrict__ bil_b,
                             const float* __restrict__ cW1, const float* __restrict__ cb1,
                             const float* __restrict__ cW2, const float* __restrict__ cb2,
                             float* __restrict__ out) {
    __shared__ int   sLo, sHi;
    __shared__ float lig[HH];
    __shared__ float inter[64];
    __shared__ float c1[32];
    int g = blockIdx.x;
    int tid = threadIdx.x;   // 64
    int is64 = g_is64;
    if (tid < 2) {
        int key = g + tid;
        int lo = 0, hi = NN;
        while (lo < hi) {
            int mid = (lo + hi) >> 1;
            if (load_idx(batch, mid, is64) < key) lo = mid + 1; else hi = mid;
        }
        if (tid == 0) sLo = lo; else sHi = lo;
    }
    __syncthreads();
    int lo = sLo, hi = sHi;
    float s0 = 0.f, s1 = 0.f;
    for (int r = lo; r < hi; r++) {
        uint u0 = __ldg((const uint*)(g_h16 + (long long)r * HH + tid * 2));
        float2 f0 = __half22float2(*(const __half2*)&u0);
        s0 += f0.x; s1 += f0.y;
    }
    float cnt = fmaxf((float)(hi - lo), 1.f);
    lig[tid * 2]     = s0 / cnt;
    lig[tid * 2 + 1] = s1 / cnt;
    __syncthreads();
    {
        float acc = bil_b[tid];
        const float* wp = &g_Wp[tid * HH];
        #pragma unroll 8
        for (int i = 0; i < HH; i++) acc += lig[i] * wp[i];
        inter[tid] = acc;
    }
    __syncthreads();
    if (tid < 32) {
        float acc = cb1[tid];
        #pragma unroll 8
        for (int o = 0; o < 64; o++) acc += inter[o] * cW1[o * 32 + tid];
        c1[tid] = fmaxf(acc, 0.f);
    }
    __syncthreads();
    if (tid == 0) {
        float acc = cb2[0];
        #pragma unroll
        for (int t = 0; t < 32; t++) acc += c1[t] * cW2[t];
        out[g] = acc;
    }
}

// ---------------- launch ---------------------------------------------------------
extern "C" void kernel_launch(void* const* d_in, const int* in_sizes, int n_in,
                              void* d_out, int out_size) {
    const float* x       = (const float*)d_in[0];
    const void*  ei      = d_in[1];
    const void*  batch   = d_in[2];
    const float* pocket  = (const float*)d_in[3];
    const float* conv0_W = (const float*)d_in[4];
    const float* conv0_b = (const float*)d_in[5];
    const float* convs_W = (const float*)d_in[6];
    const float* convs_b = (const float*)d_in[7];
    const float* bn_g    = (const float*)d_in[8];
    const float* bn_b    = (const float*)d_in[9];
    const float* bn_m    = (const float*)d_in[10];
    const float* bn_v    = (const float*)d_in[11];
    const float* pW1     = (const float*)d_in[12];
    const float* pb1     = (const float*)d_in[13];
    const float* pW2     = (const float*)d_in[14];
    const float* pb2     = (const float*)d_in[15];
    const float* bilW    = (const float*)d_in[16];
    const float* bilb    = (const float*)d_in[17];
    const float* cW1     = (const float*)d_in[18];
    const float* cb1     = (const float*)d_in[19];
    const float* cW2     = (const float*)d_in[20];
    const float* cb2     = (const float*)d_in[21];
    float* out = (float*)d_out;

    __half* h16 = nullptr; __half* u16 = nullptr; __half* w16 = nullptr; int* degp = nullptr;
    cudaGetSymbolAddress((void**)&h16, g_h16);
    cudaGetSymbolAddress((void**)&u16, g_u16);
    cudaGetSymbolAddress((void**)&w16, g_W16);
    cudaGetSymbolAddress((void**)&degp, g_deg);

    const int TB = 256;
    // CSR build + input/weight prep
    k_detect<<<1, 32>>>(ei);
    k_small<<<1, 256>>>(pocket, pW1, pb1, pW2, pb2, bilW);
    k_prep_x<<<(NN + TB - 1) / TB, TB>>>(x);
    k_w16<<<(2 * HH * HH + TB - 1) / TB, TB>>>(convs_W);
    cudaMemsetAsync(degp, 0, NN * sizeof(int));
    k_deg_count<<<(NE / 4 + TB - 1) / TB, TB>>>(ei);
    k_scanA<<<NB, 1024>>>();
    k_scanB<<<1, 32>>>();
    k_scanC<<<NB, 1024>>>();
    k_scatter<<<(NE / 4 + TB - 1) / TB, TB>>>(ei);

    int agg_blocks = (NN * 32 + TB - 1) / TB;

    // layer 0: aggregate x (7-dim) then GEMM+BN+ReLU
    k_aggx<<<(NN + TB - 1) / TB, TB>>>();
    k_gemm0<<<(NN + 31) / 32, HH>>>(conv0_W, conv0_b, bn_g, bn_b, bn_m, bn_v);
    // layers 1,2: aggregate then tensor-core GEMM
    for (int l = 1; l <= 2; l++) {
        const __half* Wl = w16 + (long long)(l - 1) * HH * HH;
        const float* b = convs_b + (l - 1) * HH;
        k_agg<<<agg_blocks, TB>>>(h16, u16);
        k_gemm_tc<<<NP / 64, 128>>>(u16, Wl, h16, b,
                                    bn_g + l * HH, bn_b + l * HH,
                                    bn_m + l * HH, bn_v + l * HH);
    }

    // pool + bilinear + classifier
    k_pool_final<<<GG, 64>>>(batch, bilb, cW1, cb1, cW2, cb2, out);
}

// round 14
// speedup vs baseline: 1.5168x; 1.0080x over previous
#include <cuda_runtime.h>
#include <cuda_fp16.h>
#include <mma.h>
using namespace nvcuda;

#define NN 50000
#define NP 50048                 // padded to 64-row multiple
#define NE 1600000
#define HH 128
#define GG 256
#define BN_EPS 1e-5f
#define NB ((NN + 1023) / 1024)

// ---------------- scratch (static device memory) ----------------------------
__device__ int    g_is64;
__device__ int    g_deg[NN];
__device__ int    g_rowoff[NN + 1];
__device__ int    g_cursor[NN];
__device__ int2   g_edge[NE];
__device__ float  g_dinv[NN];
__device__ int    g_bsum[NB];
__device__ int    g_boff[NB];
__device__ __half g_x16[NN * 8];
__device__ __half g_u016[NN * 8];
__device__ __half g_u16[NP * HH];
__device__ __half g_h16[NP * HH];
__device__ __half g_W16[2 * HH * HH];
__device__ float  g_Wp[64 * HH];

__device__ __forceinline__ int load_idx(const void* p, long long i, int is64) {
    if (is64) return (int)((const long long*)p)[i];
    return ((const int*)p)[i];
}
__device__ __forceinline__ int h2i(__half2 h) { return *reinterpret_cast<int*>(&h); }

// ---------------- merged prep: detect + deg=0 + x16 + W16 + pocket MLP --------
__global__ void k_prep(const float* __restrict__ x, const float* __restrict__ W,
                       const void* __restrict__ ei,
                       const float* __restrict__ pf,
                       const float* __restrict__ W1, const float* __restrict__ b1,
                       const float* __restrict__ W2, const float* __restrict__ b2,
                       const float* __restrict__ bilW) {
    int tid = threadIdx.x;
    if (blockIdx.x == gridDim.x - 1) {
        // pocket MLP + bilinear contraction (one block, 256 threads)
        __shared__ float t1[64];
        __shared__ float spk[64];
        if (tid < 64) {
            float acc = b1[tid];
            for (int k = 0; k < 28; k++) acc += pf[k] * W1[k * 64 + tid];
            t1[tid] = fmaxf(acc, 0.f);
        }
        __syncthreads();
        if (tid < 64) {
            float acc = b2[tid];
            for (int jj = 0; jj < 64; jj++) acc += t1[jj] * W2[jj * 64 + tid];
            spk[tid] = acc;
        }
        __syncthreads();
        for (int idx = tid; idx < 64 * HH; idx += blockDim.x) {
            int o = idx / HH, i2 = idx % HH;
            const float4* wrow = (const float4*)(bilW + ((long long)o * HH + i2) * 64);
            float acc = 0.f;
            #pragma unroll
            for (int jj = 0; jj < 16; jj++) {
                float4 w = __ldg(&wrow[jj]);
                const float4 s = *(const float4*)&spk[jj * 4];
                acc += w.x * s.x + w.y * s.y + w.z * s.z + w.w * s.w;
            }
            g_Wp[o * HH + i2] = acc;
        }
        return;
    }
    if (blockIdx.x == 0 && tid < 32) {       // dtype detect, warp 0
        const int* p = (const int*)ei;
        int nz = 0;
        #pragma unroll
        for (int r = 0; r < 4; r++) if (p[(tid + r * 32) * 2 + 1] != 0) nz = 1;
        unsigned m = __ballot_sync(0xFFFFFFFFu, nz);
        if (tid == 0) g_is64 = (m == 0u) ? 1 : 0;
    }
    int v = blockIdx.x * blockDim.x + tid;
    if (v < NN) {
        g_deg[v] = 0;
        __half h[8];
        #pragma unroll
        for (int k = 0; k < 7; k++) h[k] = __float2half_rn(x[v * 7 + k]);
        h[7] = __float2half_rn(0.f);
        *(uint4*)&g_x16[v * 8] = *(uint4*)h;
    }
    if (v < 2 * HH * HH) g_W16[v] = __float2half_rn(W[v]);
}

// ---------------- CSR build: 4 edges per thread --------------------------------
__global__ void k_deg_count(const void* ei) {
    int t = blockIdx.x * blockDim.x + threadIdx.x;
    if (t >= NE / 4) return;
    int d[4];
    if (g_is64) {
        int4 v0 = __ldg((const int4*)((const long long*)ei + NE) + t * 2);
        int4 v1 = __ldg((const int4*)((const long long*)ei + NE) + t * 2 + 1);
        d[0] = v0.x; d[1] = v0.z; d[2] = v1.x; d[3] = v1.z;
    } else {
        int4 v = __ldg((const int4*)((const int*)ei + NE) + t);
        d[0] = v.x; d[1] = v.y; d[2] = v.z; d[3] = v.w;
    }
    #pragma unroll
    for (int q = 0; q < 4; q++) atomicAdd(&g_deg[d[q]], 1);
}

__global__ void k_scanA() {
    int i = blockIdx.x * 1024 + threadIdx.x;
    int v = (i < NN) ? g_deg[i] : 0;
    int lane = threadIdx.x & 31, wid = threadIdx.x >> 5;
    int s = v;
    #pragma unroll
    for (int o = 1; o < 32; o <<= 1) {
        int t = __shfl_up_sync(0xFFFFFFFFu, s, o);
        if (lane >= o) s += t;
    }
    __shared__ int wsum[32];
    if (lane == 31) wsum[wid] = s;
    __syncthreads();
    if (wid == 0) {
        int t = wsum[lane];
        #pragma unroll
        for (int o = 1; o < 32; o <<= 1) {
            int u = __shfl_up_sync(0xFFFFFFFFu, t, o);
            if (lane >= o) t += u;
        }
        wsum[lane] = t;
    }
    __syncthreads();
    int incl = s + (wid > 0 ? wsum[wid - 1] : 0);
    if (i < NN) {
        g_rowoff[i] = incl - v;
        g_dinv[i]   = rsqrtf((float)v + 1.0f);
    }
    if (threadIdx.x == 1023) g_bsum[blockIdx.x] = incl;
}

__global__ void k_scanB() {
    int lane = threadIdx.x;
    int carry = 0;
    for (int base = 0; base < NB; base += 32) {
        int idx = base + lane;
        int v = (idx < NB) ? g_bsum[idx] : 0;
        int s = v;
        #pragma unroll
        for (int o = 1; o < 32; o <<= 1) {
            int t = __shfl_up_sync(0xFFFFFFFFu, s, o);
            if (lane >= o) s += t;
        }
        if (idx < NB) g_boff[idx] = carry + s - v;
        carry += __shfl_sync(0xFFFFFFFFu, s, 31);
    }
    if (lane == 0) g_rowoff[NN] = carry;
}

__global__ void k_scanC() {
    int i = blockIdx.x * 1024 + threadIdx.x;
    if (i < NN) {
        int v = g_rowoff[i] + g_boff[blockIdx.x];
        g_rowoff[i] = v;
        g_cursor[i] = v;
    }
}

__global__ void k_scatter(const void* ei) {
    int t = blockIdx.x * blockDim.x + threadIdx.x;
    if (t >= NE / 4) return;
    int s[4], d[4];
    if (g_is64) {
        int4 s0 = __ldg((const int4*)((const long long*)ei) + t * 2);
        int4 s1 = __ldg((const int4*)((const long long*)ei) + t * 2 + 1);
        int4 d0 = __ldg((const int4*)((const long long*)ei + NE) + t * 2);
        int4 d1 = __ldg((const int4*)((const long long*)ei + NE) + t * 2 + 1);
        s[0] = s0.x; s[1] = s0.z; s[2] = s1.x; s[3] = s1.z;
        d[0] = d0.x; d[1] = d0.z; d[2] = d1.x; d[3] = d1.z;
    } else {
        int4 sv = __ldg((const int4*)((const int*)ei) + t);
        int4 dv = __ldg((const int4*)((const int*)ei + NE) + t);
        s[0] = sv.x; s[1] = sv.y; s[2] = sv.z; s[3] = sv.w;
        d[0] = dv.x; d[1] = dv.y; d[2] = dv.z; d[3] = dv.w;
    }
    #pragma unroll
    for (int q = 0; q < 4; q++) {
        float c = g_dinv[s[q]] * g_dinv[d[q]];
        int pos = atomicAdd(&g_cursor[d[q]], 1);
        g_edge[pos] = make_int2(s[q], __float_as_int(c));
    }
}

// ---------------- layer-0 aggregation in 7-dim space ---------------------------
__global__ void k_aggx() {
    int v = blockIdx.x * blockDim.x + threadIdx.x;
    if (v >= NN) return;
    float di = g_dinv[v];
    float c0 = di * di;
    float acc[8];
    {
        uint4 u = *(const uint4*)&g_x16[v * 8];
        const __half2* hp = (const __half2*)&u;
        #pragma unroll
        for (int q = 0; q < 4; q++) {
            float2 f = __half22float2(hp[q]);
            acc[q * 2] = c0 * f.x; acc[q * 2 + 1] = c0 * f.y;
        }
    }
    int e0 = g_rowoff[v], e1 = g_rowoff[v + 1];
    int e = e0;
    for (; e + 1 < e1; e += 2) {
        int2 eA = __ldg(&g_edge[e]);
        int2 eB = __ldg(&g_edge[e + 1]);
        uint4 uA = __ldg((const uint4*)&g_x16[(long long)eA.x * 8]);
        uint4 uB = __ldg((const uint4*)&g_x16[(long long)eB.x * 8]);
        float cA = __int_as_float(eA.y), cB = __int_as_float(eB.y);
        const __half2* ha = (const __half2*)&uA;
        const __half2* hb = (const __half2*)&uB;
        #pragma unroll
        for (int q = 0; q < 4; q++) {
            float2 fa = __half22float2(ha[q]);
            float2 fb = __half22float2(hb[q]);
            acc[q * 2]     += cA * fa.x + cB * fb.x;
            acc[q * 2 + 1] += cA * fa.y + cB * fb.y;
        }
    }
    for (; e < e1; e++) {
        int2 ed = __ldg(&g_edge[e]);
        uint4 u = __ldg((const uint4*)&g_x16[(long long)ed.x * 8]);
        float c = __int_as_float(ed.y);
        const __half2* hp = (const __half2*)&u;
        #pragma unroll
        for (int q = 0; q < 4; q++) {
            float2 f = __half22float2(hp[q]);
            acc[q * 2] += c * f.x; acc[q * 2 + 1] += c * f.y;
        }
    }
    __half2 o[4];
    #pragma unroll
    for (int q = 0; q < 4; q++) o[q] = __floats2half2_rn(acc[q * 2], acc[q * 2 + 1]);
    *(uint4*)&g_u016[v * 8] = *(uint4*)o;
}

// ---------------- layer-0 GEMM + BN + ReLU -------------------------------------
__global__ void k_gemm0(const float* __restrict__ W, const float* __restrict__ bias,
                        const float* __restrict__ gamma, const float* __restrict__ beta,
                        const float* __restrict__ mean,  const float* __restrict__ var) {
    __shared__ float su[32][8];
    int row0 = blockIdx.x * 32;
    int tid = threadIdx.x;
    if (tid < 32) {
        int gr = row0 + tid;
        uint4 u = (gr < NN) ? *(const uint4*)&g_u016[gr * 8]
                            : make_uint4(0, 0, 0, 0);
        const __half2* hp = (const __half2*)&u;
        #pragma unroll
        for (int q = 0; q < 4; q++) {
            float2 f = __half22float2(hp[q]);
            su[tid][q * 2] = f.x; su[tid][q * 2 + 1] = f.y;
        }
    }
    __syncthreads();
    float w[7];
    #pragma unroll
    for (int k = 0; k < 7; k++) w[k] = W[k * HH + tid];
    float rs = rsqrtf(var[tid] + BN_EPS);
    float scale = gamma[tid] * rs;
    float shift = (bias[tid] - mean[tid]) * scale + beta[tid];
    #pragma unroll 4
    for (int r = 0; r < 32; r++) {
        int gr = row0 + r;
        if (gr < NN) {
            float acc = 0.f;
            #pragma unroll
            for (int k = 0; k < 7; k++) acc += su[r][k] * w[k];
            g_h16[(long long)gr * HH + tid] = __float2half_rn(fmaxf(acc * scale + shift, 0.f));
        }
    }
}

// ---------------- 128-dim aggregation ------------------------------------------
__global__ void k_agg(const __half* __restrict__ in16, __half* __restrict__ out16) {
    int v = (blockIdx.x * blockDim.x + threadIdx.x) >> 5;
    int lane = threadIdx.x & 31;
    if (v >= NN) return;
    float di = g_dinv[v];
    float c0 = di * di;
    int j = lane * 4;
    uint2 us = __ldg((const uint2*)(in16 + (long long)v * HH + j));
    float2 s0 = __half22float2(*(const __half2*)&us.x);
    float2 s1 = __half22float2(*(const __half2*)&us.y);
    float ax = c0 * s0.x, ay = c0 * s0.y, az = c0 * s1.x, aw = c0 * s1.y;
    int e0 = g_rowoff[v], e1 = g_rowoff[v + 1];
    int e = e0;
    for (; e + 7 < e1; e += 8) {
        int2 ed[8];
        uint2 u[8];
        #pragma unroll
        for (int q = 0; q < 8; q++) ed[q] = __ldg(&g_edge[e + q]);
        #pragma unroll
        for (int q = 0; q < 8; q++)
            u[q] = __ldg((const uint2*)(in16 + (long long)ed[q].x * HH + j));
        #pragma unroll
        for (int q = 0; q < 8; q++) {
            float c = __int_as_float(ed[q].y);
            float2 f0 = __half22float2(*(const __half2*)&u[q].x);
            float2 f1 = __half22float2(*(const __half2*)&u[q].y);
            ax += c * f0.x; ay += c * f0.y; az += c * f1.x; aw += c * f1.y;
        }
    }
    for (; e < e1; e++) {
        int2 ed = __ldg(&g_edge[e]);
        float c = __int_as_float(ed.y);
        uint2 u = __ldg((const uint2*)(in16 + (long long)ed.x * HH + j));
        float2 f0 = __half22float2(*(const __half2*)&u.x);
        float2 f1 = __half22float2(*(const __half2*)&u.y);
        ax += c * f0.x; ay += c * f0.y; az += c * f1.x; aw += c * f1.y;
    }
    uint2 o;
    *(__half2*)&o.x = __floats2half2_rn(ax, ay);
    *(__half2*)&o.y = __floats2half2_rn(az, aw);
    *(uint2*)(out16 + (long long)v * HH + j) = o;
}

// ---------------- tensor-core GEMM + fused BN/ReLU -----------------------------
__global__ void __launch_bounds__(128) k_gemm_tc(const __half* __restrict__ A16,
                                                 const __half* __restrict__ W16,
                                                 __half* __restrict__ C16,
                                                 const float* __restrict__ bias,
                                                 const float* __restrict__ gamma,
                                                 const float* __restrict__ beta,
                                                 const float* __restrict__ mean,
                                                 const float* __restrict__ var) {
    __shared__ float sC[4][16 * HH];     // 32 KB
    __shared__ float s_sc[HH], s_sh[HH];
    int tid = threadIdx.x;
    int warp = tid >> 5, lane = tid & 31;
    {
        float rs = rsqrtf(var[tid] + BN_EPS);
        float sc = gamma[tid] * rs;
        s_sc[tid] = sc;
        s_sh[tid] = (bias[tid] - mean[tid]) * sc + beta[tid];
    }
    __syncthreads();

    int row0 = blockIdx.x * 64 + warp * 16;   // always < NP (padded)
    wmma::fragment<wmma::accumulator, 16, 16, 16, float> c_frag[8];
    #pragma unroll
    for (int n = 0; n < 8; n++) wmma::fill_fragment(c_frag[n], 0.0f);

    for (int k = 0; k < HH; k += 16) {
        wmma::fragment<wmma::matrix_a, 16, 16, 16, __half, wmma::row_major> a_frag;
        wmma::load_matrix_sync(a_frag, A16 + (long long)row0 * HH + k, HH);
        #pragma unroll
        for (int n = 0; n < 8; n++) {
            wmma::fragment<wmma::matrix_b, 16, 16, 16, __half, wmma::row_major> b_frag;
            wmma::load_matrix_sync(b_frag, W16 + k * HH + n * 16, HH);
            wmma::mma_sync(c_frag[n], a_frag, b_frag, c_frag[n]);
        }
    }
    float* myC = sC[warp];
    #pragma unroll
    for (int n = 0; n < 8; n++)
        wmma::store_matrix_sync(myC + n * 16, c_frag[n], HH, wmma::mem_row_major);
    __syncwarp();

    for (int gI = lane; gI < 16 * 16; gI += 32) {
        int r = gI >> 4, c8 = gI & 15;
        float o[8];
        #pragma unroll
        for (int q = 0; q < 8; q++) {
            int col = c8 * 8 + q;
            o[q] = fmaxf(myC[r * HH + col] * s_sc[col] + s_sh[col], 0.f);
        }
        __half2 h0 = __floats2half2_rn(o[0], o[1]);
        __half2 h1 = __floats2half2_rn(o[2], o[3]);
        __half2 h2 = __floats2half2_rn(o[4], o[5]);
        __half2 h3 = __floats2half2_rn(o[6], o[7]);
        int4 pk = make_int4(h2i(h0), h2i(h1), h2i(h2), h2i(h3));
        *(int4*)&C16[(long long)(row0 + r) * HH + c8 * 8] = pk;
    }
}

// ---------------- pool + bilinear + classifier ---------------------------------
__global__ void k_pool_final(const void* __restrict__ batch,
                             const float* __restrict__ bil_b,
                             const float* __restrict__ cW1, const float* __restrict__ cb1,
                             const float* __restrict__ cW2, const float* __restrict__ cb2,
                             float* __restrict__ out) {
    __shared__ int   sLo, sHi;
    __shared__ float lig[HH];
    __shared__ float inter[64];
    __shared__ float c1[32];
    int g = blockIdx.x;
    int tid = threadIdx.x;   // 64
    int is64 = g_is64;
    if (tid < 2) {
        int key = g + tid;
        int lo = 0, hi = NN;
        while (lo < hi) {
            int mid = (lo + hi) >> 1;
            if (load_idx(batch, mid, is64) < key) lo = mid + 1; else hi = mid;
        }
        if (tid == 0) sLo = lo; else sHi = lo;
    }
    __syncthreads();
    int lo = sLo, hi = sHi;
    float s0 = 0.f, s1 = 0.f;
    for (int r = lo; r < hi; r++) {
        uint u0 = __ldg((const uint*)(g_h16 + (long long)r * HH + tid * 2));
        float2 f0 = __half22float2(*(const __half2*)&u0);
        s0 += f0.x; s1 += f0.y;
    }
    float cnt = fmaxf((float)(hi - lo), 1.f);
    lig[tid * 2]     = s0 / cnt;
    lig[tid * 2 + 1] = s1 / cnt;
    __syncthreads();
    {
        float acc = bil_b[tid];
        const float* wp = &g_Wp[tid * HH];
        #pragma unroll 8
        for (int i = 0; i < HH; i++) acc += lig[i] * wp[i];
        inter[tid] = acc;
    }
    __syncthreads();
    if (tid < 32) {
        float acc = cb1[tid];
        #pragma unroll 8
        for (int o = 0; o < 64; o++) acc += inter[o] * cW1[o * 32 + tid];
        c1[tid] = fmaxf(acc, 0.f);
    }
    __syncthreads();
    if (tid == 0) {
        float acc = cb2[0];
        #pragma unroll
        for (int t = 0; t < 32; t++) acc += c1[t] * cW2[t];
        out[g] = acc;
    }
}

// ---------------- launch ---------------------------------------------------------
extern "C" void kernel_launch(void* const* d_in, const int* in_sizes, int n_in,
                              void* d_out, int out_size) {
    const float* x       = (const float*)d_in[0];
    const void*  ei      = d_in[1];
    const void*  batch   = d_in[2];
    const float* pocket  = (const float*)d_in[3];
    const float* conv0_W = (const float*)d_in[4];
    const float* conv0_b = (const float*)d_in[5];
    const float* convs_W = (const float*)d_in[6];
    const float* convs_b = (const float*)d_in[7];
    const float* bn_g    = (const float*)d_in[8];
    const float* bn_b    = (const float*)d_in[9];
    const float* bn_m    = (const float*)d_in[10];
    const float* bn_v    = (const float*)d_in[11];
    const float* pW1     = (const float*)d_in[12];
    const float* pb1     = (const float*)d_in[13];
    const float* pW2     = (const float*)d_in[14];
    const float* pb2     = (const float*)d_in[15];
    const float* bilW    = (const float*)d_in[16];
    const float* bilb    = (const float*)d_in[17];
    const float* cW1     = (const float*)d_in[18];
    const float* cb1     = (const float*)d_in[19];
    const float* cW2     = (const float*)d_in[20];
    const float* cb2     = (const float*)d_in[21];
    float* out = (float*)d_out;

    __half* h16 = nullptr; __half* u16 = nullptr; __half* w16 = nullptr;
    cudaGetSymbolAddress((void**)&h16, g_h16);
    cudaGetSymbolAddress((void**)&u16, g_u16);
    cudaGetSymbolAddress((void**)&w16, g_W16);

    const int TB = 256;
    // merged prep (detect + deg=0 + x16 + W16 + pocket MLP), then CSR build
    int prep_blocks = (NN + TB - 1) / TB + 1;    // last block = pocket MLP
    k_prep<<<prep_blocks, TB>>>(x, convs_W, ei, pocket, pW1, pb1, pW2, pb2, bilW);
    k_deg_count<<<(NE / 4 + TB - 1) / TB, TB>>>(ei);
    k_scanA<<<NB, 1024>>>();
    k_scanB<<<1, 32>>>();
    k_scanC<<<NB, 1024>>>();
    k_scatter<<<(NE / 4 + TB - 1) / TB, TB>>>(ei);

    int agg_blocks = (NN * 32 + TB - 1) / TB;

    // layer 0: aggregate x (7-dim) then GEMM+BN+ReLU
    k_aggx<<<(NN + TB - 1) / TB, TB>>>();
    k_gemm0<<<(NN + 31) / 32, HH>>>(conv0_W, conv0_b, bn_g, bn_b, bn_m, bn_v);
    // layers 1,2: aggregate then tensor-core GEMM
    for (int l = 1; l <= 2; l++) {
        const __half* Wl = w16 + (long long)(l - 1) * HH * HH;
        const float* b = convs_b + (l - 1) * HH;
        k_agg<<<agg_blocks, TB>>>(h16, u16);
        k_gemm_tc<<<NP / 64, 128>>>(u16, Wl, h16, b,
                                    bn_g + l * HH, bn_b + l * HH,
                                    bn_m + l * HH, bn_v + l * HH);
    }

    // pool + bilinear + classifier
    k_pool_final<<<GG, 64>>>(batch, bilb, cW1, cb1, cW2, cb2, out);
}

// round 15
// speedup vs baseline: 1.5265x; 1.0064x over previous
#include <cuda_runtime.h>
#include <cuda_fp16.h>
#include <mma.h>
using namespace nvcuda;

#define NN 50000
#define NP 50048                 // padded to 64-row multiple
#define NE 1600000
#define HH 128
#define GG 256
#define BN_EPS 1e-5f
#define NB ((NN + 1023) / 1024)

// ---------------- scratch (static device memory) ----------------------------
__device__ int    g_is64;
__device__ int    g_deg[NN];
__device__ int    g_rowoff[NN + 1];
__device__ int    g_cursor[NN];
__device__ int2   g_edge[NE];
__device__ float  g_dinv[NN];
__device__ int    g_bsum[NB];
__device__ __half g_x16[NN * 8];
__device__ __half g_u016[NN * 8];
__device__ __half g_u16[NP * HH];
__device__ __half g_h16[NP * HH];
__device__ __half g_W16[2 * HH * HH];
__device__ float  g_Wp[64 * HH];

__device__ __forceinline__ int load_idx(const void* p, long long i, int is64) {
    if (is64) return (int)((const long long*)p)[i];
    return ((const int*)p)[i];
}
__device__ __forceinline__ int h2i(__half2 h) { return *reinterpret_cast<int*>(&h); }

// ---------------- merged prep: detect + deg=0 + x16 + W16 + pocket MLP --------
__global__ void k_prep(const float* __restrict__ x, const float* __restrict__ W,
                       const void* __restrict__ ei,
                       const float* __restrict__ pf,
                       const float* __restrict__ W1, const float* __restrict__ b1,
                       const float* __restrict__ W2, const float* __restrict__ b2,
                       const float* __restrict__ bilW) {
    int tid = threadIdx.x;
    if (blockIdx.x == gridDim.x - 1) {
        // pocket MLP + bilinear contraction (one block, 256 threads)
        __shared__ float t1[64];
        __shared__ float spk[64];
        if (tid < 64) {
            float acc = b1[tid];
            for (int k = 0; k < 28; k++) acc += pf[k] * W1[k * 64 + tid];
            t1[tid] = fmaxf(acc, 0.f);
        }
        __syncthreads();
        if (tid < 64) {
            float acc = b2[tid];
            for (int jj = 0; jj < 64; jj++) acc += t1[jj] * W2[jj * 64 + tid];
            spk[tid] = acc;
        }
        __syncthreads();
        for (int idx = tid; idx < 64 * HH; idx += blockDim.x) {
            int o = idx / HH, i2 = idx % HH;
            const float4* wrow = (const float4*)(bilW + ((long long)o * HH + i2) * 64);
            float acc = 0.f;
            #pragma unroll
            for (int jj = 0; jj < 16; jj++) {
                float4 w = __ldg(&wrow[jj]);
                const float4 s = *(const float4*)&spk[jj * 4];
                acc += w.x * s.x + w.y * s.y + w.z * s.z + w.w * s.w;
            }
            g_Wp[o * HH + i2] = acc;
        }
        return;
    }
    if (blockIdx.x == 0 && tid < 32) {       // dtype detect, warp 0
        const int* p = (const int*)ei;
        int nz = 0;
        #pragma unroll
        for (int r = 0; r < 4; r++) if (p[(tid + r * 32) * 2 + 1] != 0) nz = 1;
        unsigned m = __ballot_sync(0xFFFFFFFFu, nz);
        if (tid == 0) g_is64 = (m == 0u) ? 1 : 0;
    }
    int v = blockIdx.x * blockDim.x + tid;
    if (v < NN) {
        g_deg[v] = 0;
        __half h[8];
        #pragma unroll
        for (int k = 0; k < 7; k++) h[k] = __float2half_rn(x[v * 7 + k]);
        h[7] = __float2half_rn(0.f);
        *(uint4*)&g_x16[v * 8] = *(uint4*)h;
    }
    if (v < 2 * HH * HH) g_W16[v] = __float2half_rn(W[v]);
}

// ---------------- CSR build: 4 edges per thread --------------------------------
__global__ void k_deg_count(const void* ei) {
    int t = blockIdx.x * blockDim.x + threadIdx.x;
    if (t >= NE / 4) return;
    int d[4];
    if (g_is64) {
        int4 v0 = __ldg((const int4*)((const long long*)ei + NE) + t * 2);
        int4 v1 = __ldg((const int4*)((const long long*)ei + NE) + t * 2 + 1);
        d[0] = v0.x; d[1] = v0.z; d[2] = v1.x; d[3] = v1.z;
    } else {
        int4 v = __ldg((const int4*)((const int*)ei + NE) + t);
        d[0] = v.x; d[1] = v.y; d[2] = v.z; d[3] = v.w;
    }
    #pragma unroll
    for (int q = 0; q < 4; q++) atomicAdd(&g_deg[d[q]], 1);
}

__global__ void k_scanA() {
    int i = blockIdx.x * 1024 + threadIdx.x;
    int v = (i < NN) ? g_deg[i] : 0;
    int lane = threadIdx.x & 31, wid = threadIdx.x >> 5;
    int s = v;
    #pragma unroll
    for (int o = 1; o < 32; o <<= 1) {
        int t = __shfl_up_sync(0xFFFFFFFFu, s, o);
        if (lane >= o) s += t;
    }
    __shared__ int wsum[32];
    if (lane == 31) wsum[wid] = s;
    __syncthreads();
    if (wid == 0) {
        int t = wsum[lane];
        #pragma unroll
        for (int o = 1; o < 32; o <<= 1) {
            int u = __shfl_up_sync(0xFFFFFFFFu, t, o);
            if (lane >= o) t += u;
        }
        wsum[lane] = t;
    }
    __syncthreads();
    int incl = s + (wid > 0 ? wsum[wid - 1] : 0);
    if (i < NN) {
        g_rowoff[i] = incl - v;
        g_dinv[i]   = rsqrtf((float)v + 1.0f);
    }
    if (threadIdx.x == 1023) g_bsum[blockIdx.x] = incl;
}

// lookback scan-fixup + cursor init (scanB folded in)
__global__ void k_scanC() {
    __shared__ int soff;
    int b = blockIdx.x;
    if (threadIdx.x < 32) {
        int lane = threadIdx.x;
        int part = 0;
        for (int i = lane; i < b; i += 32) part += g_bsum[i];
        #pragma unroll
        for (int o = 16; o > 0; o >>= 1) part += __shfl_xor_sync(0xFFFFFFFFu, part, o);
        if (lane == 0) {
            soff = part;
            if (b == NB - 1) g_rowoff[NN] = part + g_bsum[NB - 1];
        }
    }
    __syncthreads();
    int i = b * 1024 + threadIdx.x;
    if (i < NN) {
        int v = g_rowoff[i] + soff;
        g_rowoff[i] = v;
        g_cursor[i] = v;
    }
}

__global__ void k_scatter(const void* ei) {
    int t = blockIdx.x * blockDim.x + threadIdx.x;
    if (t >= NE / 4) return;
    int s[4], d[4];
    if (g_is64) {
        int4 s0 = __ldg((const int4*)((const long long*)ei) + t * 2);
        int4 s1 = __ldg((const int4*)((const long long*)ei) + t * 2 + 1);
        int4 d0 = __ldg((const int4*)((const long long*)ei + NE) + t * 2);
        int4 d1 = __ldg((const int4*)((const long long*)ei + NE) + t * 2 + 1);
        s[0] = s0.x; s[1] = s0.z; s[2] = s1.x; s[3] = s1.z;
        d[0] = d0.x; d[1] = d0.z; d[2] = d1.x; d[3] = d1.z;
    } else {
        int4 sv = __ldg((const int4*)((const int*)ei) + t);
        int4 dv = __ldg((const int4*)((const int*)ei + NE) + t);
        s[0] = sv.x; s[1] = sv.y; s[2] = sv.z; s[3] = sv.w;
        d[0] = dv.x; d[1] = dv.y; d[2] = dv.z; d[3] = dv.w;
    }
    #pragma unroll
    for (int q = 0; q < 4; q++) {
        float c = g_dinv[s[q]] * g_dinv[d[q]];
        int pos = atomicAdd(&g_cursor[d[q]], 1);
        g_edge[pos] = make_int2(s[q], __float_as_int(c));
    }
}

// ---------------- layer-0 aggregation in 7-dim space ---------------------------
__global__ void k_aggx() {
    int v = blockIdx.x * blockDim.x + threadIdx.x;
    if (v >= NN) return;
    float di = g_dinv[v];
    float c0 = di * di;
    float acc[8];
    {
        uint4 u = *(const uint4*)&g_x16[v * 8];
        const __half2* hp = (const __half2*)&u;
        #pragma unroll
        for (int q = 0; q < 4; q++) {
            float2 f = __half22float2(hp[q]);
            acc[q * 2] = c0 * f.x; acc[q * 2 + 1] = c0 * f.y;
        }
    }
    int e0 = g_rowoff[v], e1 = g_rowoff[v + 1];
    int e = e0;
    for (; e + 1 < e1; e += 2) {
        int2 eA = __ldg(&g_edge[e]);
        int2 eB = __ldg(&g_edge[e + 1]);
        uint4 uA = __ldg((const uint4*)&g_x16[(long long)eA.x * 8]);
        uint4 uB = __ldg((const uint4*)&g_x16[(long long)eB.x * 8]);
        float cA = __int_as_float(eA.y), cB = __int_as_float(eB.y);
        const __half2* ha = (const __half2*)&uA;
        const __half2* hb = (const __half2*)&uB;
        #pragma unroll
        for (int q = 0; q < 4; q++) {
            float2 fa = __half22float2(ha[q]);
            float2 fb = __half22float2(hb[q]);
            acc[q * 2]     += cA * fa.x + cB * fb.x;
            acc[q * 2 + 1] += cA * fa.y + cB * fb.y;
        }
    }
    for (; e < e1; e++) {
        int2 ed = __ldg(&g_edge[e]);
        uint4 u = __ldg((const uint4*)&g_x16[(long long)ed.x * 8]);
        float c = __int_as_float(ed.y);
        const __half2* hp = (const __half2*)&u;
        #pragma unroll
        for (int q = 0; q < 4; q++) {
            float2 f = __half22float2(hp[q]);
            acc[q * 2] += c * f.x; acc[q * 2 + 1] += c * f.y;
        }
    }
    __half2 o[4];
    #pragma unroll
    for (int q = 0; q < 4; q++) o[q] = __floats2half2_rn(acc[q * 2], acc[q * 2 + 1]);
    *(uint4*)&g_u016[v * 8] = *(uint4*)o;
}

// ---------------- layer-0 GEMM + BN + ReLU -------------------------------------
__global__ void k_gemm0(const float* __restrict__ W, const float* __restrict__ bias,
                        const float* __restrict__ gamma, const float* __restrict__ beta,
                        const float* __restrict__ mean,  const float* __restrict__ var) {
    __shared__ float su[32][8];
    int row0 = blockIdx.x * 32;
    int tid = threadIdx.x;
    if (tid < 32) {
        int gr = row0 + tid;
        uint4 u = (gr < NN) ? *(const uint4*)&g_u016[gr * 8]
                            : make_uint4(0, 0, 0, 0);
        const __half2* hp = (const __half2*)&u;
        #pragma unroll
        for (int q = 0; q < 4; q++) {
            float2 f = __half22float2(hp[q]);
            su[tid][q * 2] = f.x; su[tid][q * 2 + 1] = f.y;
        }
    }
    __syncthreads();
    float w[7];
    #pragma unroll
    for (int k = 0; k < 7; k++) w[k] = W[k * HH + tid];
    float rs = rsqrtf(var[tid] + BN_EPS);
    float scale = gamma[tid] * rs;
    float shift = (bias[tid] - mean[tid]) * scale + beta[tid];
    #pragma unroll 4
    for (int r = 0; r < 32; r++) {
        int gr = row0 + r;
        if (gr < NN) {
            float acc = 0.f;
            #pragma unroll
            for (int k = 0; k < 7; k++) acc += su[r][k] * w[k];
            g_h16[(long long)gr * HH + tid] = __float2half_rn(fmaxf(acc * scale + shift, 0.f));
        }
    }
}

// ---------------- 128-dim aggregation ------------------------------------------
__global__ void k_agg(const __half* __restrict__ in16, __half* __restrict__ out16) {
    int v = (blockIdx.x * blockDim.x + threadIdx.x) >> 5;
    int lane = threadIdx.x & 31;
    if (v >= NN) return;
    float di = g_dinv[v];
    float c0 = di * di;
    int j = lane * 4;
    uint2 us = __ldg((const uint2*)(in16 + (long long)v * HH + j));
    float2 s0 = __half22float2(*(const __half2*)&us.x);
    float2 s1 = __half22float2(*(const __half2*)&us.y);
    float ax = c0 * s0.x, ay = c0 * s0.y, az = c0 * s1.x, aw = c0 * s1.y;
    int e0 = g_rowoff[v], e1 = g_rowoff[v + 1];
    int e = e0;
    for (; e + 7 < e1; e += 8) {
        int2 ed[8];
        uint2 u[8];
        #pragma unroll
        for (int q = 0; q < 8; q++) ed[q] = __ldg(&g_edge[e + q]);
        #pragma unroll
        for (int q = 0; q < 8; q++)
            u[q] = __ldg((const uint2*)(in16 + (long long)ed[q].x * HH + j));
        #pragma unroll
        for (int q = 0; q < 8; q++) {
            float c = __int_as_float(ed[q].y);
            float2 f0 = __half22float2(*(const __half2*)&u[q].x);
            float2 f1 = __half22float2(*(const __half2*)&u[q].y);
            ax += c * f0.x; ay += c * f0.y; az += c * f1.x; aw += c * f1.y;
        }
    }
    for (; e < e1; e++) {
        int2 ed = __ldg(&g_edge[e]);
        float c = __int_as_float(ed.y);
        uint2 u = __ldg((const uint2*)(in16 + (long long)ed.x * HH + j));
        float2 f0 = __half22float2(*(const __half2*)&u.x);
        float2 f1 = __half22float2(*(const __half2*)&u.y);
        ax += c * f0.x; ay += c * f0.y; az += c * f1.x; aw += c * f1.y;
    }
    uint2 o;
    *(__half2*)&o.x = __floats2half2_rn(ax, ay);
    *(__half2*)&o.y = __floats2half2_rn(az, aw);
    *(uint2*)(out16 + (long long)v * HH + j) = o;
}

// ---------------- tensor-core GEMM + fused BN/ReLU -----------------------------
__global__ void __launch_bounds__(128) k_gemm_tc(const __half* __restrict__ A16,
                                                 const __half* __restrict__ W16,
                                                 __half* __restrict__ C16,
                                                 const float* __restrict__ bias,
                                                 const float* __restrict__ gamma,
                                                 const float* __restrict__ beta,
                                                 const float* __restrict__ mean,
                                                 const float* __restrict__ var) {
    __shared__ float sC[4][16 * HH];     // 32 KB
    __shared__ float s_sc[HH], s_sh[HH];
    int tid = threadIdx.x;
    int warp = tid >> 5, lane = tid & 31;
    {
        float rs = rsqrtf(var[tid] + BN_EPS);
        float sc = gamma[tid] * rs;
        s_sc[tid] = sc;
        s_sh[tid] = (bias[tid] - mean[tid]) * sc + beta[tid];
    }
    __syncthreads();

    int row0 = blockIdx.x * 64 + warp * 16;   // always < NP (padded)
    wmma::fragment<wmma::accumulator, 16, 16, 16, float> c_frag[8];
    #pragma unroll
    for (int n = 0; n < 8; n++) wmma::fill_fragment(c_frag[n], 0.0f);

    for (int k = 0; k < HH; k += 16) {
        wmma::fragment<wmma::matrix_a, 16, 16, 16, __half, wmma::row_major> a_frag;
        wmma::load_matrix_sync(a_frag, A16 + (long long)row0 * HH + k, HH);
        #pragma unroll
        for (int n = 0; n < 8; n++) {
            wmma::fragment<wmma::matrix_b, 16, 16, 16, __half, wmma::row_major> b_frag;
            wmma::load_matrix_sync(b_frag, W16 + k * HH + n * 16, HH);
            wmma::mma_sync(c_frag[n], a_frag, b_frag, c_frag[n]);
        }
    }
    float* myC = sC[warp];
    #pragma unroll
    for (int n = 0; n < 8; n++)
        wmma::store_matrix_sync(myC + n * 16, c_frag[n], HH, wmma::mem_row_major);
    __syncwarp();

    for (int gI = lane; gI < 16 * 16; gI += 32) {
        int r = gI >> 4, c8 = gI & 15;
        float o[8];
        #pragma unroll
        for (int q = 0; q < 8; q++) {
            int col = c8 * 8 + q;
            o[q] = fmaxf(myC[r * HH + col] * s_sc[col] + s_sh[col], 0.f);
        }
        __half2 h0 = __floats2half2_rn(o[0], o[1]);
        __half2 h1 = __floats2half2_rn(o[2], o[3]);
        __half2 h2 = __floats2half2_rn(o[4], o[5]);
        __half2 h3 = __floats2half2_rn(o[6], o[7]);
        int4 pk = make_int4(h2i(h0), h2i(h1), h2i(h2), h2i(h3));
        *(int4*)&C16[(long long)(row0 + r) * HH + c8 * 8] = pk;
    }
}

// ---------------- pool + bilinear + classifier ---------------------------------
__global__ void k_pool_final(const void* __restrict__ batch,
                             const float* __restrict__ bil_b,
                             const float* __restrict__ cW1, const float* __restrict__ cb1,
                             const float* __restrict__ cW2, const float* __restrict__ cb2,
                             float* __restrict__ out) {
    __shared__ int   sLo, sHi;
    __shared__ float lig[HH];
    __shared__ float inter[64];
    __shared__ float c1[32];
    int g = blockIdx.x;
    int tid = threadIdx.x;   // 64
    int is64 = g_is64;
    if (tid < 2) {
        int key = g + tid;
        int lo = 0, hi = NN;
        while (lo < hi) {
            int mid = (lo + hi) >> 1;
            if (load_idx(batch, mid, is64) < key) lo = mid + 1; else hi = mid;
        }
        if (tid == 0) sLo = lo; else sHi = lo;
    }
    __syncthreads();
    int lo = sLo, hi = sHi;
    float s0 = 0.f, s1 = 0.f;
    for (int r = lo; r < hi; r++) {
        uint u0 = __ldg((const uint*)(g_h16 + (long long)r * HH + tid * 2));
        float2 f0 = __half22float2(*(const __half2*)&u0);
        s0 += f0.x; s1 += f0.y;
    }
    float cnt = fmaxf((float)(hi - lo), 1.f);
    lig[tid * 2]     = s0 / cnt;
    lig[tid * 2 + 1] = s1 / cnt;
    __syncthreads();
    {
        float acc = bil_b[tid];
        const float* wp = &g_Wp[tid * HH];
        #pragma unroll 8
        for (int i = 0; i < HH; i++) acc += lig[i] * wp[i];
        inter[tid] = acc;
    }
    __syncthreads();
    if (tid < 32) {
        float acc = cb1[tid];
        #pragma unroll 8
        for (int o = 0; o < 64; o++) acc += inter[o] * cW1[o * 32 + tid];
        c1[tid] = fmaxf(acc, 0.f);
    }
    __syncthreads();
    if (tid == 0) {
        float acc = cb2[0];
        #pragma unroll
        for (int t = 0; t < 32; t++) acc += c1[t] * cW2[t];
        out[g] = acc;
    }
}

// ---------------- launch ---------------------------------------------------------
extern "C" void kernel_launch(void* const* d_in, const int* in_sizes, int n_in,
                              void* d_out, int out_size) {
    const float* x       = (const float*)d_in[0];
    const void*  ei      = d_in[1];
    const void*  batch   = d_in[2];
    const float* pocket  = (const float*)d_in[3];
    const float* conv0_W = (const float*)d_in[4];
    const float* conv0_b = (const float*)d_in[5];
    const float* convs_W = (const float*)d_in[6];
    const float* convs_b = (const float*)d_in[7];
    const float* bn_g    = (const float*)d_in[8];
    const float* bn_b    = (const float*)d_in[9];
    const float* bn_m    = (const float*)d_in[10];
    const float* bn_v    = (const float*)d_in[11];
    const float* pW1     = (const float*)d_in[12];
    const float* pb1     = (const float*)d_in[13];
    const float* pW2     = (const float*)d_in[14];
    const float* pb2     = (const float*)d_in[15];
    const float* bilW    = (const float*)d_in[16];
    const float* bilb    = (const float*)d_in[17];
    const float* cW1     = (const float*)d_in[18];
    const float* cb1     = (const float*)d_in[19];
    const float* cW2     = (const float*)d_in[20];
    const float* cb2     = (const float*)d_in[21];
    float* out = (float*)d_out;

    __half* h16 = nullptr; __half* u16 = nullptr; __half* w16 = nullptr;
    cudaGetSymbolAddress((void**)&h16, g_h16);
    cudaGetSymbolAddress((void**)&u16, g_u16);
    cudaGetSymbolAddress((void**)&w16, g_W16);

    const int TB = 256;
    int prep_blocks = (NN + TB - 1) / TB + 1;    // last block = pocket MLP
    k_prep<<<prep_blocks, TB>>>(x, convs_W, ei, pocket, pW1, pb1, pW2, pb2, bilW);
    k_deg_count<<<(NE / 4 + TB - 1) / TB, TB>>>(ei);
    k_scanA<<<NB, 1024>>>();
    k_scanC<<<NB, 1024>>>();
    k_scatter<<<(NE / 4 + TB - 1) / TB, TB>>>(ei);

    int agg_blocks = (NN * 32 + TB - 1) / TB;

    // layer 0: aggregate x (7-dim) then GEMM+BN+ReLU
    k_aggx<<<(NN + TB - 1) / TB, TB>>>();
    k_gemm0<<<(NN + 31) / 32, HH>>>(conv0_W, conv0_b, bn_g, bn_b, bn_m, bn_v);
    // layers 1,2: aggregate then tensor-core GEMM
    for (int l = 1; l <= 2; l++) {
        const __half* Wl = w16 + (long long)(l - 1) * HH * HH;
        const float* b = convs_b + (l - 1) * HH;
        k_agg<<<agg_blocks, TB>>>(h16, u16);
        k_gemm_tc<<<NP / 64, 128>>>(u16, Wl, h16, b,
                                    bn_g + l * HH, bn_b + l * HH,
                                    bn_m + l * HH, bn_v + l * HH);
    }

    // pool + bilinear + classifier
    k_pool_final<<<GG, 64>>>(batch, bilb, cW1, cb1, cW2, cb2, out);
}

// round 16
// speedup vs baseline: 1.5270x; 1.0003x over previous
#include <cuda_runtime.h>
#include <cuda_fp16.h>
#include <mma.h>
using namespace nvcuda;

#define NN 50000
#define NP 50048                 // padded to 64-row multiple
#define NE 1600000
#define HH 128
#define GG 256
#define BN_EPS 1e-5f
#define NB ((NN + 1023) / 1024)

// ---------------- scratch (static device memory) ----------------------------
__device__ int    g_is64;
__device__ int    g_deg[NN];
__device__ int    g_rowoff[NN + 1];
__device__ int    g_cursor[NN];
__device__ int2   g_edge[NE];
__device__ float  g_dinv[NN];
__device__ int    g_bsum[NB];
__device__ __half g_x16[NN * 8];
__device__ __half g_u16[NP * HH];
__device__ __half g_h16[NP * HH];
__device__ __half g_W16[2 * HH * HH];
__device__ float  g_Wp[64 * HH];

__device__ __forceinline__ int load_idx(const void* p, long long i, int is64) {
    if (is64) return (int)((const long long*)p)[i];
    return ((const int*)p)[i];
}
__device__ __forceinline__ int h2i(__half2 h) { return *reinterpret_cast<int*>(&h); }

// ---------------- merged prep: detect + deg=0 + x16 + W16 + pocket MLP --------
__global__ void k_prep(const float* __restrict__ x, const float* __restrict__ W,
                       const void* __restrict__ ei,
                       const float* __restrict__ pf,
                       const float* __restrict__ W1, const float* __restrict__ b1,
                       const float* __restrict__ W2, const float* __restrict__ b2,
                       const float* __restrict__ bilW) {
    int tid = threadIdx.x;
    if (blockIdx.x == gridDim.x - 1) {
        // pocket MLP + bilinear contraction (one block, 256 threads)
        __shared__ float t1[64];
        __shared__ float spk[64];
        if (tid < 64) {
            float acc = b1[tid];
            for (int k = 0; k < 28; k++) acc += pf[k] * W1[k * 64 + tid];
            t1[tid] = fmaxf(acc, 0.f);
        }
        __syncthreads();
        if (tid < 64) {
            float acc = b2[tid];
            for (int jj = 0; jj < 64; jj++) acc += t1[jj] * W2[jj * 64 + tid];
            spk[tid] = acc;
        }
        __syncthreads();
        for (int idx = tid; idx < 64 * HH; idx += blockDim.x) {
            int o = idx / HH, i2 = idx % HH;
            const float4* wrow = (const float4*)(bilW + ((long long)o * HH + i2) * 64);
            float acc = 0.f;
            #pragma unroll
            for (int jj = 0; jj < 16; jj++) {
                float4 w = __ldg(&wrow[jj]);
                const float4 s = *(const float4*)&spk[jj * 4];
                acc += w.x * s.x + w.y * s.y + w.z * s.z + w.w * s.w;
            }
            g_Wp[o * HH + i2] = acc;
        }
        return;
    }
    if (blockIdx.x == 0 && tid < 32) {       // dtype detect, warp 0
        const int* p = (const int*)ei;
        int nz = 0;
        #pragma unroll
        for (int r = 0; r < 4; r++) if (p[(tid + r * 32) * 2 + 1] != 0) nz = 1;
        unsigned m = __ballot_sync(0xFFFFFFFFu, nz);
        if (tid == 0) g_is64 = (m == 0u) ? 1 : 0;
    }
    int v = blockIdx.x * blockDim.x + tid;
    if (v < NN) {
        g_deg[v] = 0;
        __half h[8];
        #pragma unroll
        for (int k = 0; k < 7; k++) h[k] = __float2half_rn(x[v * 7 + k]);
        h[7] = __float2half_rn(0.f);
        *(uint4*)&g_x16[v * 8] = *(uint4*)h;
    }
    if (v < 2 * HH * HH) g_W16[v] = __float2half_rn(W[v]);
}

// ---------------- CSR build: 4 edges per thread --------------------------------
__global__ void k_deg_count(const void* ei) {
    int t = blockIdx.x * blockDim.x + threadIdx.x;
    if (t >= NE / 4) return;
    int d[4];
    if (g_is64) {
        int4 v0 = __ldg((const int4*)((const long long*)ei + NE) + t * 2);
        int4 v1 = __ldg((const int4*)((const long long*)ei + NE) + t * 2 + 1);
        d[0] = v0.x; d[1] = v0.z; d[2] = v1.x; d[3] = v1.z;
    } else {
        int4 v = __ldg((const int4*)((const int*)ei + NE) + t);
        d[0] = v.x; d[1] = v.y; d[2] = v.z; d[3] = v.w;
    }
    #pragma unroll
    for (int q = 0; q < 4; q++) atomicAdd(&g_deg[d[q]], 1);
}

__global__ void k_scanA() {
    int i = blockIdx.x * 1024 + threadIdx.x;
    int v = (i < NN) ? g_deg[i] : 0;
    int lane = threadIdx.x & 31, wid = threadIdx.x >> 5;
    int s = v;
    #pragma unroll
    for (int o = 1; o < 32; o <<= 1) {
        int t = __shfl_up_sync(0xFFFFFFFFu, s, o);
        if (lane >= o) s += t;
    }
    __shared__ int wsum[32];
    if (lane == 31) wsum[wid] = s;
    __syncthreads();
    if (wid == 0) {
        int t = wsum[lane];
        #pragma unroll
        for (int o = 1; o < 32; o <<= 1) {
            int u = __shfl_up_sync(0xFFFFFFFFu, t, o);
            if (lane >= o) t += u;
        }
        wsum[lane] = t;
    }
    __syncthreads();
    int incl = s + (wid > 0 ? wsum[wid - 1] : 0);
    if (i < NN) {
        g_rowoff[i] = incl - v;
        g_dinv[i]   = rsqrtf((float)v + 1.0f);
    }
    if (threadIdx.x == 1023) g_bsum[blockIdx.x] = incl;
}

// lookback scan-fixup + cursor init (scanB folded in)
__global__ void k_scanC() {
    __shared__ int soff;
    int b = blockIdx.x;
    if (threadIdx.x < 32) {
        int lane = threadIdx.x;
        int part = 0;
        for (int i = lane; i < b; i += 32) part += g_bsum[i];
        #pragma unroll
        for (int o = 16; o > 0; o >>= 1) part += __shfl_xor_sync(0xFFFFFFFFu, part, o);
        if (lane == 0) {
            soff = part;
            if (b == NB - 1) g_rowoff[NN] = part + g_bsum[NB - 1];
        }
    }
    __syncthreads();
    int i = b * 1024 + threadIdx.x;
    if (i < NN) {
        int v = g_rowoff[i] + soff;
        g_rowoff[i] = v;
        g_cursor[i] = v;
    }
}

__global__ void k_scatter(const void* ei) {
    int t = blockIdx.x * blockDim.x + threadIdx.x;
    if (t >= NE / 4) return;
    int s[4], d[4];
    if (g_is64) {
        int4 s0 = __ldg((const int4*)((const long long*)ei) + t * 2);
        int4 s1 = __ldg((const int4*)((const long long*)ei) + t * 2 + 1);
        int4 d0 = __ldg((const int4*)((const long long*)ei + NE) + t * 2);
        int4 d1 = __ldg((const int4*)((const long long*)ei + NE) + t * 2 + 1);
        s[0] = s0.x; s[1] = s0.z; s[2] = s1.x; s[3] = s1.z;
        d[0] = d0.x; d[1] = d0.z; d[2] = d1.x; d[3] = d1.z;
    } else {
        int4 sv = __ldg((const int4*)((const int*)ei) + t);
        int4 dv = __ldg((const int4*)((const int*)ei + NE) + t);
        s[0] = sv.x; s[1] = sv.y; s[2] = sv.z; s[3] = sv.w;
        d[0] = dv.x; d[1] = dv.y; d[2] = dv.z; d[3] = dv.w;
    }
    #pragma unroll
    for (int q = 0; q < 4; q++) {
        float c = g_dinv[s[q]] * g_dinv[d[q]];
        int pos = atomicAdd(&g_cursor[d[q]], 1);
        g_edge[pos] = make_int2(s[q], __float_as_int(c));
    }
}

// ---------------- fused layer-0: 7-dim agg (regs->smem) + GEMM + BN + ReLU ----
__global__ void __launch_bounds__(128) k_layer0(const float* __restrict__ W,
                                                const float* __restrict__ bias,
                                                const float* __restrict__ gamma,
                                                const float* __restrict__ beta,
                                                const float* __restrict__ mean,
                                                const float* __restrict__ var) {
    __shared__ float su[128][8];
    int row0 = blockIdx.x * 128;
    int tid = threadIdx.x;
    int v = row0 + tid;
    float acc[8] = {};
    if (v < NN) {
        float di = g_dinv[v];
        float c0 = di * di;
        uint4 u = *(const uint4*)&g_x16[v * 8];
        const __half2* hp = (const __half2*)&u;
        #pragma unroll
        for (int q = 0; q < 4; q++) {
            float2 f = __half22float2(hp[q]);
            acc[q * 2] = c0 * f.x; acc[q * 2 + 1] = c0 * f.y;
        }
        int e0 = g_rowoff[v], e1 = g_rowoff[v + 1];
        int e = e0;
        for (; e + 1 < e1; e += 2) {
            int2 eA = __ldg(&g_edge[e]);
            int2 eB = __ldg(&g_edge[e + 1]);
            uint4 uA = __ldg((const uint4*)&g_x16[(long long)eA.x * 8]);
            uint4 uB = __ldg((const uint4*)&g_x16[(long long)eB.x * 8]);
            float cA = __int_as_float(eA.y), cB = __int_as_float(eB.y);
            const __half2* ha = (const __half2*)&uA;
            const __half2* hb = (const __half2*)&uB;
            #pragma unroll
            for (int q = 0; q < 4; q++) {
                float2 fa = __half22float2(ha[q]);
                float2 fb = __half22float2(hb[q]);
                acc[q * 2]     += cA * fa.x + cB * fb.x;
                acc[q * 2 + 1] += cA * fa.y + cB * fb.y;
            }
        }
        for (; e < e1; e++) {
            int2 ed = __ldg(&g_edge[e]);
            uint4 u2 = __ldg((const uint4*)&g_x16[(long long)ed.x * 8]);
            float c = __int_as_float(ed.y);
            const __half2* hp2 = (const __half2*)&u2;
            #pragma unroll
            for (int q = 0; q < 4; q++) {
                float2 f = __half22float2(hp2[q]);
                acc[q * 2] += c * f.x; acc[q * 2 + 1] += c * f.y;
            }
        }
    }
    #pragma unroll
    for (int q = 0; q < 8; q++) su[tid][q] = acc[q];
    __syncthreads();
    // gemm: thread = column
    float w[7];
    #pragma unroll
    for (int k = 0; k < 7; k++) w[k] = W[k * HH + tid];
    float rs = rsqrtf(var[tid] + BN_EPS);
    float scale = gamma[tid] * rs;
    float shift = (bias[tid] - mean[tid]) * scale + beta[tid];
    int rmax = min(128, NN - row0);
    for (int r = 0; r < rmax; r++) {
        float a = 0.f;
        #pragma unroll
        for (int k = 0; k < 7; k++) a += su[r][k] * w[k];
        g_h16[(long long)(row0 + r) * HH + tid] = __float2half_rn(fmaxf(a * scale + shift, 0.f));
    }
}

// ---------------- 128-dim aggregation ------------------------------------------
__global__ void k_agg(const __half* __restrict__ in16, __half* __restrict__ out16) {
    int v = (blockIdx.x * blockDim.x + threadIdx.x) >> 5;
    int lane = threadIdx.x & 31;
    if (v >= NN) return;
    float di = g_dinv[v];
    float c0 = di * di;
    int j = lane * 4;
    uint2 us = __ldg((const uint2*)(in16 + (long long)v * HH + j));
    float2 s0 = __half22float2(*(const __half2*)&us.x);
    float2 s1 = __half22float2(*(const __half2*)&us.y);
    float ax = c0 * s0.x, ay = c0 * s0.y, az = c0 * s1.x, aw = c0 * s1.y;
    int e0 = g_rowoff[v], e1 = g_rowoff[v + 1];
    int e = e0;
    for (; e + 7 < e1; e += 8) {
        int2 ed[8];
        uint2 u[8];
        #pragma unroll
        for (int q = 0; q < 8; q++) ed[q] = __ldg(&g_edge[e + q]);
        #pragma unroll
        for (int q = 0; q < 8; q++)
            u[q] = __ldg((const uint2*)(in16 + (long long)ed[q].x * HH + j));
        #pragma unroll
        for (int q = 0; q < 8; q++) {
            float c = __int_as_float(ed[q].y);
            float2 f0 = __half22float2(*(const __half2*)&u[q].x);
            float2 f1 = __half22float2(*(const __half2*)&u[q].y);
            ax += c * f0.x; ay += c * f0.y; az += c * f1.x; aw += c * f1.y;
        }
    }
    for (; e < e1; e++) {
        int2 ed = __ldg(&g_edge[e]);
        float c = __int_as_float(ed.y);
        uint2 u = __ldg((const uint2*)(in16 + (long long)ed.x * HH + j));
        float2 f0 = __half22float2(*(const __half2*)&u.x);
        float2 f1 = __half22float2(*(const __half2*)&u.y);
        ax += c * f0.x; ay += c * f0.y; az += c * f1.x; aw += c * f1.y;
    }
    uint2 o;
    *(__half2*)&o.x = __floats2half2_rn(ax, ay);
    *(__half2*)&o.y = __floats2half2_rn(az, aw);
    *(uint2*)(out16 + (long long)v * HH + j) = o;
}

// ---------------- tensor-core GEMM + fused BN/ReLU -----------------------------
__global__ void __launch_bounds__(128) k_gemm_tc(const __half* __restrict__ A16,
                                                 const __half* __restrict__ W16,
                                                 __half* __restrict__ C16,
                                                 const float* __restrict__ bias,
                                                 const float* __restrict__ gamma,
                                                 const float* __restrict__ beta,
                                                 const float* __restrict__ mean,
                                                 const float* __restrict__ var) {
    __shared__ float sC[4][16 * HH];     // 32 KB
    __shared__ float s_sc[HH], s_sh[HH];
    int tid = threadIdx.x;
    int warp = tid >> 5, lane = tid & 31;
    {
        float rs = rsqrtf(var[tid] + BN_EPS);
        float sc = gamma[tid] * rs;
        s_sc[tid] = sc;
        s_sh[tid] = (bias[tid] - mean[tid]) * sc + beta[tid];
    }
    __syncthreads();

    int row0 = blockIdx.x * 64 + warp * 16;   // always < NP (padded)
    wmma::fragment<wmma::accumulator, 16, 16, 16, float> c_frag[8];
    #pragma unroll
    for (int n = 0; n < 8; n++) wmma::fill_fragment(c_frag[n], 0.0f);

    for (int k = 0; k < HH; k += 16) {
        wmma::fragment<wmma::matrix_a, 16, 16, 16, __half, wmma::row_major> a_frag;
        wmma::load_matrix_sync(a_frag, A16 + (long long)row0 * HH + k, HH);
        #pragma unroll
        for (int n = 0; n < 8; n++) {
            wmma::fragment<wmma::matrix_b, 16, 16, 16, __half, wmma::row_major> b_frag;
            wmma::load_matrix_sync(b_frag, W16 + k * HH + n * 16, HH);
            wmma::mma_sync(c_frag[n], a_frag, b_frag, c_frag[n]);
        }
    }
    float* myC = sC[warp];
    #pragma unroll
    for (int n = 0; n < 8; n++)
        wmma::store_matrix_sync(myC + n * 16, c_frag[n], HH, wmma::mem_row_major);
    __syncwarp();

    for (int gI = lane; gI < 16 * 16; gI += 32) {
        int r = gI >> 4, c8 = gI & 15;
        float o[8];
        #pragma unroll
        for (int q = 0; q < 8; q++) {
            int col = c8 * 8 + q;
            o[q] = fmaxf(myC[r * HH + col] * s_sc[col] + s_sh[col], 0.f);
        }
        __half2 h0 = __floats2half2_rn(o[0], o[1]);
        __half2 h1 = __floats2half2_rn(o[2], o[3]);
        __half2 h2 = __floats2half2_rn(o[4], o[5]);
        __half2 h3 = __floats2half2_rn(o[6], o[7]);
        int4 pk = make_int4(h2i(h0), h2i(h1), h2i(h2), h2i(h3));
        *(int4*)&C16[(long long)(row0 + r) * HH + c8 * 8] = pk;
    }
}

// ---------------- pool + bilinear + classifier ---------------------------------
__global__ void k_pool_final(const void* __restrict__ batch,
                             const float* __restrict__ bil_b,
                             const float* __restrict__ cW1, const float* __restrict__ cb1,
                             const float* __restrict__ cW2, const float* __restrict__ cb2,
                             float* __restrict__ out) {
    __shared__ int   sLo, sHi;
    __shared__ float lig[HH];
    __shared__ float inter[64];
    __shared__ float c1[32];
    int g = blockIdx.x;
    int tid = threadIdx.x;   // 64
    int is64 = g_is64;
    if (tid < 2) {
        int key = g + tid;
        int lo = 0, hi = NN;
        while (lo < hi) {
            int mid = (lo + hi) >> 1;
            if (load_idx(batch, mid, is64) < key) lo = mid + 1; else hi = mid;
        }
        if (tid == 0) sLo = lo; else sHi = lo;
    }
    __syncthreads();
    int lo = sLo, hi = sHi;
    float s0 = 0.f, s1 = 0.f;
    for (int r = lo; r < hi; r++) {
        uint u0 = __ldg((const uint*)(g_h16 + (long long)r * HH + tid * 2));
        float2 f0 = __half22float2(*(const __half2*)&u0);
        s0 += f0.x; s1 += f0.y;
    }
    float cnt = fmaxf((float)(hi - lo), 1.f);
    lig[tid * 2]     = s0 / cnt;
    lig[tid * 2 + 1] = s1 / cnt;
    __syncthreads();
    {
        float acc = bil_b[tid];
        const float* wp = &g_Wp[tid * HH];
        #pragma unroll 8
        for (int i = 0; i < HH; i++) acc += lig[i] * wp[i];
        inter[tid] = acc;
    }
    __syncthreads();
    if (tid < 32) {
        float acc = cb1[tid];
        #pragma unroll 8
        for (int o = 0; o < 64; o++) acc += inter[o] * cW1[o * 32 + tid];
        c1[tid] = fmaxf(acc, 0.f);
    }
    __syncthreads();
    if (tid == 0) {
        float acc = cb2[0];
        #pragma unroll
        for (int t = 0; t < 32; t++) acc += c1[t] * cW2[t];
        out[g] = acc;
    }
}

// ---------------- launch ---------------------------------------------------------
extern "C" void kernel_launch(void* const* d_in, const int* in_sizes, int n_in,
                              void* d_out, int out_size) {
    const float* x       = (const float*)d_in[0];
    const void*  ei      = d_in[1];
    const void*  batch   = d_in[2];
    const float* pocket  = (const float*)d_in[3];
    const float* conv0_W = (const float*)d_in[4];
    const float* conv0_b = (const float*)d_in[5];
    const float* convs_W = (const float*)d_in[6];
    const float* convs_b = (const float*)d_in[7];
    const float* bn_g    = (const float*)d_in[8];
    const float* bn_b    = (const float*)d_in[9];
    const float* bn_m    = (const float*)d_in[10];
    const float* bn_v    = (const float*)d_in[11];
    const float* pW1     = (const float*)d_in[12];
    const float* pb1     = (const float*)d_in[13];
    const float* pW2     = (const float*)d_in[14];
    const float* pb2     = (const float*)d_in[15];
    const float* bilW    = (const float*)d_in[16];
    const float* bilb    = (const float*)d_in[17];
    const float* cW1     = (const float*)d_in[18];
    const float* cb1     = (const float*)d_in[19];
    const float* cW2     = (const float*)d_in[20];
    const float* cb2     = (const float*)d_in[21];
    float* out = (float*)d_out;

    __half* h16 = nullptr; __half* u16 = nullptr; __half* w16 = nullptr;
    cudaGetSymbolAddress((void**)&h16, g_h16);
    cudaGetSymbolAddress((void**)&u16, g_u16);
    cudaGetSymbolAddress((void**)&w16, g_W16);

    const int TB = 256;
    int prep_blocks = (NN + TB - 1) / TB + 1;    // last block = pocket MLP
    k_prep<<<prep_blocks, TB>>>(x, convs_W, ei, pocket, pW1, pb1, pW2, pb2, bilW);
    k_deg_count<<<(NE / 4 + TB - 1) / TB, TB>>>(ei);
    k_scanA<<<NB, 1024>>>();
    k_scanC<<<NB, 1024>>>();
    k_scatter<<<(NE / 4 + TB - 1) / TB, TB>>>(ei);

    int agg_blocks = (NN * 32 + TB - 1) / TB;

    // layer 0: fused 7-dim agg + GEMM + BN + ReLU
    k_layer0<<<(NN + 127) / 128, 128>>>(conv0_W, conv0_b, bn_g, bn_b, bn_m, bn_v);
    // layers 1,2: aggregate then tensor-core GEMM
    for (int l = 1; l <= 2; l++) {
        const __half* Wl = w16 + (long long)(l - 1) * HH * HH;
        const float* b = convs_b + (l - 1) * HH;
        k_agg<<<agg_blocks, TB>>>(h16, u16);
        k_gemm_tc<<<NP / 64, 128>>>(u16, Wl, h16, b,
                                    bn_g + l * HH, bn_b + l * HH,
                                    bn_m + l * HH, bn_v + l * HH);
    }

    // pool + bilinear + classifier
    k_pool_final<<<GG, 64>>>(batch, bilb, cW1, cb1, cW2, cb2, out);
}

// round 17
// speedup vs baseline: 1.5371x; 1.0067x over previous
#include <cuda_runtime.h>
#include <cuda_fp16.h>
#include <mma.h>
using namespace nvcuda;

#define NN 50000
#define NP 50048                 // padded to 64-row multiple
#define NE 1600000
#define HH 128
#define GG 256
#define BN_EPS 1e-5f
#define NB ((NN + 1023) / 1024)

// ---------------- scratch (static device memory) ----------------------------
__device__ int    g_is64;
__device__ int    g_deg[NN];
__device__ int    g_rowoff[NN + 1];
__device__ int    g_cursor[NN];
__device__ int2   g_edge[NE];
__device__ float  g_dinv[NN];
__device__ int    g_bpub[NB];         // lookback: block total + 1 (0 = not ready)
__device__ __half g_x16[NN * 8];
__device__ __half g_u16[NP * HH];
__device__ __half g_h16[NP * HH];
__device__ __half g_W16[2 * HH * HH];
__device__ float  g_Wp[64 * HH];

__device__ __forceinline__ int load_idx(const void* p, long long i, int is64) {
    if (is64) return (int)((const long long*)p)[i];
    return ((const int*)p)[i];
}
__device__ __forceinline__ int h2i(__half2 h) { return *reinterpret_cast<int*>(&h); }

// ---------------- merged prep: detect + deg=0 + bpub=0 + x16 + W16 + pMLP -----
__global__ void k_prep(const float* __restrict__ x, const float* __restrict__ W,
                       const void* __restrict__ ei,
                       const float* __restrict__ pf,
                       const float* __restrict__ W1, const float* __restrict__ b1,
                       const float* __restrict__ W2, const float* __restrict__ b2,
                       const float* __restrict__ bilW) {
    int tid = threadIdx.x;
    if (blockIdx.x == gridDim.x - 1) {
        // pocket MLP + bilinear contraction (one block, 256 threads)
        __shared__ float t1[64];
        __shared__ float spk[64];
        if (tid < 64) {
            float acc = b1[tid];
            for (int k = 0; k < 28; k++) acc += pf[k] * W1[k * 64 + tid];
            t1[tid] = fmaxf(acc, 0.f);
        }
        __syncthreads();
        if (tid < 64) {
            float acc = b2[tid];
            for (int jj = 0; jj < 64; jj++) acc += t1[jj] * W2[jj * 64 + tid];
            spk[tid] = acc;
        }
        __syncthreads();
        for (int idx = tid; idx < 64 * HH; idx += blockDim.x) {
            int o = idx / HH, i2 = idx % HH;
            const float4* wrow = (const float4*)(bilW + ((long long)o * HH + i2) * 64);
            float acc = 0.f;
            #pragma unroll
            for (int jj = 0; jj < 16; jj++) {
                float4 w = __ldg(&wrow[jj]);
                const float4 s = *(const float4*)&spk[jj * 4];
                acc += w.x * s.x + w.y * s.y + w.z * s.z + w.w * s.w;
            }
            g_Wp[o * HH + i2] = acc;
        }
        return;
    }
    if (blockIdx.x == 0 && tid < 32) {       // dtype detect, warp 0
        const int* p = (const int*)ei;
        int nz = 0;
        #pragma unroll
        for (int r = 0; r < 4; r++) if (p[(tid + r * 32) * 2 + 1] != 0) nz = 1;
        unsigned m = __ballot_sync(0xFFFFFFFFu, nz);
        if (tid == 0) g_is64 = (m == 0u) ? 1 : 0;
    }
    int v = blockIdx.x * blockDim.x + tid;
    if (v < NB) g_bpub[v] = 0;
    if (v < NN) {
        g_deg[v] = 0;
        __half h[8];
        #pragma unroll
        for (int k = 0; k < 7; k++) h[k] = __float2half_rn(x[v * 7 + k]);
        h[7] = __float2half_rn(0.f);
        *(uint4*)&g_x16[v * 8] = *(uint4*)h;
    }
    if (v < 2 * HH * HH) g_W16[v] = __float2half_rn(W[v]);
}

// ---------------- CSR build: 4 edges per thread --------------------------------
__global__ void k_deg_count(const void* ei) {
    int t = blockIdx.x * blockDim.x + threadIdx.x;
    if (t >= NE / 4) return;
    int d[4];
    if (g_is64) {
        int4 v0 = __ldg((const int4*)((const long long*)ei + NE) + t * 2);
        int4 v1 = __ldg((const int4*)((const long long*)ei + NE) + t * 2 + 1);
        d[0] = v0.x; d[1] = v0.z; d[2] = v1.x; d[3] = v1.z;
    } else {
        int4 v = __ldg((const int4*)((const int*)ei + NE) + t);
        d[0] = v.x; d[1] = v.y; d[2] = v.z; d[3] = v.w;
    }
    #pragma unroll
    for (int q = 0; q < 4; q++) atomicAdd(&g_deg[d[q]], 1);
}

// ---------------- single-pass scan (decoupled lookback) + cursor init ----------
__global__ void k_scan() {
    int b = blockIdx.x;
    int i = b * 1024 + threadIdx.x;
    int v = (i < NN) ? g_deg[i] : 0;
    int lane = threadIdx.x & 31, wid = threadIdx.x >> 5;
    int s = v;
    #pragma unroll
    for (int o = 1; o < 32; o <<= 1) {
        int t = __shfl_up_sync(0xFFFFFFFFu, s, o);
        if (lane >= o) s += t;
    }
    __shared__ int wsum[32];
    __shared__ int soff;
    if (lane == 31) wsum[wid] = s;
    __syncthreads();
    if (wid == 0) {
        int t = wsum[lane];
        #pragma unroll
        for (int o = 1; o < 32; o <<= 1) {
            int u = __shfl_up_sync(0xFFFFFFFFu, t, o);
            if (lane >= o) t += u;
        }
        wsum[lane] = t;
    }
    __syncthreads();
    int incl = s + (wid > 0 ? wsum[wid - 1] : 0);
    int btotal = wsum[31];
    // publish this block's total (value+1; 0 = not ready)
    if (threadIdx.x == 0) atomicExch(&g_bpub[b], btotal + 1);
    // warp 0: lookback over predecessors
    if (wid == 0) {
        int part = 0;
        for (int p = lane; p < b; p += 32) {
            int val;
            do { val = atomicAdd(&g_bpub[p], 0); } while (val == 0);
            part += val - 1;
        }
        #pragma unroll
        for (int o = 16; o > 0; o >>= 1) part += __shfl_xor_sync(0xFFFFFFFFu, part, o);
        if (lane == 0) {
            soff = part;
            if (b == NB - 1) g_rowoff[NN] = part + btotal;
        }
    }
    __syncthreads();
    if (i < NN) {
        int r = soff + incl - v;
        g_rowoff[i] = r;
        g_cursor[i] = r;
        g_dinv[i]   = rsqrtf((float)v + 1.0f);
    }
}

__global__ void k_scatter(const void* ei) {
    int t = blockIdx.x * blockDim.x + threadIdx.x;
    if (t >= NE / 4) return;
    int s[4], d[4];
    if (g_is64) {
        int4 s0 = __ldg((const int4*)((const long long*)ei) + t * 2);
        int4 s1 = __ldg((const int4*)((const long long*)ei) + t * 2 + 1);
        int4 d0 = __ldg((const int4*)((const long long*)ei + NE) + t * 2);
        int4 d1 = __ldg((const int4*)((const long long*)ei + NE) + t * 2 + 1);
        s[0] = s0.x; s[1] = s0.z; s[2] = s1.x; s[3] = s1.z;
        d[0] = d0.x; d[1] = d0.z; d[2] = d1.x; d[3] = d1.z;
    } else {
        int4 sv = __ldg((const int4*)((const int*)ei) + t);
        int4 dv = __ldg((const int4*)((const int*)ei + NE) + t);
        s[0] = sv.x; s[1] = sv.y; s[2] = sv.z; s[3] = sv.w;
        d[0] = dv.x; d[1] = dv.y; d[2] = dv.z; d[3] = dv.w;
    }
    #pragma unroll
    for (int q = 0; q < 4; q++) {
        float c = g_dinv[s[q]] * g_dinv[d[q]];
        int pos = atomicAdd(&g_cursor[d[q]], 1);
        g_edge[pos] = make_int2(s[q], __float_as_int(c));
    }
}

// ---------------- fused layer-0: 7-dim agg (regs->smem) + GEMM + BN + ReLU ----
__global__ void __launch_bounds__(128) k_layer0(const float* __restrict__ W,
                                                const float* __restrict__ bias,
                                                const float* __restrict__ gamma,
                                                const float* __restrict__ beta,
                                                const float* __restrict__ mean,
                                                const float* __restrict__ var) {
    __shared__ float su[128][8];
    int row0 = blockIdx.x * 128;
    int tid = threadIdx.x;
    int v = row0 + tid;
    float acc[8] = {};
    if (v < NN) {
        float di = g_dinv[v];
        float c0 = di * di;
        uint4 u = *(const uint4*)&g_x16[v * 8];
        const __half2* hp = (const __half2*)&u;
        #pragma unroll
        for (int q = 0; q < 4; q++) {
            float2 f = __half22float2(hp[q]);
            acc[q * 2] = c0 * f.x; acc[q * 2 + 1] = c0 * f.y;
        }
        int e0 = g_rowoff[v], e1 = g_rowoff[v + 1];
        int e = e0;
        for (; e + 1 < e1; e += 2) {
            int2 eA = __ldg(&g_edge[e]);
            int2 eB = __ldg(&g_edge[e + 1]);
            uint4 uA = __ldg((const uint4*)&g_x16[(long long)eA.x * 8]);
            uint4 uB = __ldg((const uint4*)&g_x16[(long long)eB.x * 8]);
            float cA = __int_as_float(eA.y), cB = __int_as_float(eB.y);
            const __half2* ha = (const __half2*)&uA;
            const __half2* hb = (const __half2*)&uB;
            #pragma unroll
            for (int q = 0; q < 4; q++) {
                float2 fa = __half22float2(ha[q]);
                float2 fb = __half22float2(hb[q]);
                acc[q * 2]     += cA * fa.x + cB * fb.x;
                acc[q * 2 + 1] += cA * fa.y + cB * fb.y;
            }
        }
        for (; e < e1; e++) {
            int2 ed = __ldg(&g_edge[e]);
            uint4 u2 = __ldg((const uint4*)&g_x16[(long long)ed.x * 8]);
            float c = __int_as_float(ed.y);
            const __half2* hp2 = (const __half2*)&u2;
            #pragma unroll
            for (int q = 0; q < 4; q++) {
                float2 f = __half22float2(hp2[q]);
                acc[q * 2] += c * f.x; acc[q * 2 + 1] += c * f.y;
            }
        }
    }
    #pragma unroll
    for (int q = 0; q < 8; q++) su[tid][q] = acc[q];
    __syncthreads();
    float w[7];
    #pragma unroll
    for (int k = 0; k < 7; k++) w[k] = W[k * HH + tid];
    float rs = rsqrtf(var[tid] + BN_EPS);
    float scale = gamma[tid] * rs;
    float shift = (bias[tid] - mean[tid]) * scale + beta[tid];
    int rmax = min(128, NN - row0);
    for (int r = 0; r < rmax; r++) {
        float a = 0.f;
        #pragma unroll
        for (int k = 0; k < 7; k++) a += su[r][k] * w[k];
        g_h16[(long long)(row0 + r) * HH + tid] = __float2half_rn(fmaxf(a * scale + shift, 0.f));
    }
}

// ---------------- 128-dim aggregation ------------------------------------------
__global__ void k_agg(const __half* __restrict__ in16, __half* __restrict__ out16) {
    int v = (blockIdx.x * blockDim.x + threadIdx.x) >> 5;
    int lane = threadIdx.x & 31;
    if (v >= NN) return;
    float di = g_dinv[v];
    float c0 = di * di;
    int j = lane * 4;
    uint2 us = __ldg((const uint2*)(in16 + (long long)v * HH + j));
    float2 s0 = __half22float2(*(const __half2*)&us.x);
    float2 s1 = __half22float2(*(const __half2*)&us.y);
    float ax = c0 * s0.x, ay = c0 * s0.y, az = c0 * s1.x, aw = c0 * s1.y;
    int e0 = g_rowoff[v], e1 = g_rowoff[v + 1];
    int e = e0;
    for (; e + 7 < e1; e += 8) {
        int2 ed[8];
        uint2 u[8];
        #pragma unroll
        for (int q = 0; q < 8; q++) ed[q] = __ldg(&g_edge[e + q]);
        #pragma unroll
        for (int q = 0; q < 8; q++)
            u[q] = __ldg((const uint2*)(in16 + (long long)ed[q].x * HH + j));
        #pragma unroll
        for (int q = 0; q < 8; q++) {
            float c = __int_as_float(ed[q].y);
            float2 f0 = __half22float2(*(const __half2*)&u[q].x);
            float2 f1 = __half22float2(*(const __half2*)&u[q].y);
            ax += c * f0.x; ay += c * f0.y; az += c * f1.x; aw += c * f1.y;
        }
    }
    for (; e < e1; e++) {
        int2 ed = __ldg(&g_edge[e]);
        float c = __int_as_float(ed.y);
        uint2 u = __ldg((const uint2*)(in16 + (long long)ed.x * HH + j));
        float2 f0 = __half22float2(*(const __half2*)&u.x);
        float2 f1 = __half22float2(*(const __half2*)&u.y);
        ax += c * f0.x; ay += c * f0.y; az += c * f1.x; aw += c * f1.y;
    }
    uint2 o;
    *(__half2*)&o.x = __floats2half2_rn(ax, ay);
    *(__half2*)&o.y = __floats2half2_rn(az, aw);
    *(uint2*)(out16 + (long long)v * HH + j) = o;
}

// ---------------- tensor-core GEMM + fused BN/ReLU -----------------------------
__global__ void __launch_bounds__(128) k_gemm_tc(const __half* __restrict__ A16,
                                                 const __half* __restrict__ W16,
                                                 __half* __restrict__ C16,
                                                 const float* __restrict__ bias,
                                                 const float* __restrict__ gamma,
                                                 const float* __restrict__ beta,
                                                 const float* __restrict__ mean,
                                                 const float* __restrict__ var) {
    __shared__ float sC[4][16 * HH];     // 32 KB
    __shared__ float s_sc[HH], s_sh[HH];
    int tid = threadIdx.x;
    int warp = tid >> 5, lane = tid & 31;
    {
        float rs = rsqrtf(var[tid] + BN_EPS);
        float sc = gamma[tid] * rs;
        s_sc[tid] = sc;
        s_sh[tid] = (bias[tid] - mean[tid]) * sc + beta[tid];
    }
    __syncthreads();

    int row0 = blockIdx.x * 64 + warp * 16;   // always < NP (padded)
    wmma::fragment<wmma::accumulator, 16, 16, 16, float> c_frag[8];
    #pragma unroll
    for (int n = 0; n < 8; n++) wmma::fill_fragment(c_frag[n], 0.0f);

    for (int k = 0; k < HH; k += 16) {
        wmma::fragment<wmma::matrix_a, 16, 16, 16, __half, wmma::row_major> a_frag;
        wmma::load_matrix_sync(a_frag, A16 + (long long)row0 * HH + k, HH);
        #pragma unroll
        for (int n = 0; n < 8; n++) {
            wmma::fragment<wmma::matrix_b, 16, 16, 16, __half, wmma::row_major> b_frag;
            wmma::load_matrix_sync(b_frag, W16 + k * HH + n * 16, HH);
            wmma::mma_sync(c_frag[n], a_frag, b_frag, c_frag[n]);
        }
    }
    float* myC = sC[warp];
    #pragma unroll
    for (int n = 0; n < 8; n++)
        wmma::store_matrix_sync(myC + n * 16, c_frag[n], HH, wmma::mem_row_major);
    __syncwarp();

    for (int gI = lane; gI < 16 * 16; gI += 32) {
        int r = gI >> 4, c8 = gI & 15;
        float o[8];
        #pragma unroll
        for (int q = 0; q < 8; q++) {
            int col = c8 * 8 + q;
            o[q] = fmaxf(myC[r * HH + col] * s_sc[col] + s_sh[col], 0.f);
        }
        __half2 h0 = __floats2half2_rn(o[0], o[1]);
        __half2 h1 = __floats2half2_rn(o[2], o[3]);
        __half2 h2 = __floats2half2_rn(o[4], o[5]);
        __half2 h3 = __floats2half2_rn(o[6], o[7]);
        int4 pk = make_int4(h2i(h0), h2i(h1), h2i(h2), h2i(h3));
        *(int4*)&C16[(long long)(row0 + r) * HH + c8 * 8] = pk;
    }
}

// ---------------- pool + bilinear + classifier ---------------------------------
__global__ void k_pool_final(const void* __restrict__ batch,
                             const float* __restrict__ bil_b,
                             const float* __restrict__ cW1, const float* __restrict__ cb1,
                             const float* __restrict__ cW2, const float* __restrict__ cb2,
                             float* __restrict__ out) {
    __shared__ int   sLo, sHi;
    __shared__ float lig[HH];
    __shared__ float inter[64];
    __shared__ float c1[32];
    int g = blockIdx.x;
    int tid = threadIdx.x;   // 64
    int is64 = g_is64;
    if (tid < 2) {
        int key = g + tid;
        int lo = 0, hi = NN;
        while (lo < hi) {
            int mid = (lo + hi) >> 1;
            if (load_idx(batch, mid, is64) < key) lo = mid + 1; else hi = mid;
        }
        if (tid == 0) sLo = lo; else sHi = lo;
    }
    __syncthreads();
    int lo = sLo, hi = sHi;
    float s0 = 0.f, s1 = 0.f;
    for (int r = lo; r < hi; r++) {
        uint u0 = __ldg((const uint*)(g_h16 + (long long)r * HH + tid * 2));
        float2 f0 = __half22float2(*(const __half2*)&u0);
        s0 += f0.x; s1 += f0.y;
    }
    float cnt = fmaxf((float)(hi - lo), 1.f);
    lig[tid * 2]     = s0 / cnt;
    lig[tid * 2 + 1] = s1 / cnt;
    __syncthreads();
    {
        float acc = bil_b[tid];
        const float* wp = &g_Wp[tid * HH];
        #pragma unroll 8
        for (int i = 0; i < HH; i++) acc += lig[i] * wp[i];
        inter[tid] = acc;
    }
    __syncthreads();
    if (tid < 32) {
        float acc = cb1[tid];
        #pragma unroll 8
        for (int o = 0; o < 64; o++) acc += inter[o] * cW1[o * 32 + tid];
        c1[tid] = fmaxf(acc, 0.f);
    }
    __syncthreads();
    if (tid == 0) {
        float acc = cb2[0];
        #pragma unroll
        for (int t = 0; t < 32; t++) acc += c1[t] * cW2[t];
        out[g] = acc;
    }
}

// ---------------- launch ---------------------------------------------------------
extern "C" void kernel_launch(void* const* d_in, const int* in_sizes, int n_in,
                              void* d_out, int out_size) {
    const float* x       = (const float*)d_in[0];
    const void*  ei      = d_in[1];
    const void*  batch   = d_in[2];
    const float* pocket  = (const float*)d_in[3];
    const float* conv0_W = (const float*)d_in[4];
    const float* conv0_b = (const float*)d_in[5];
    const float* convs_W = (const float*)d_in[6];
    const float* convs_b = (const float*)d_in[7];
    const float* bn_g    = (const float*)d_in[8];
    const float* bn_b    = (const float*)d_in[9];
    const float* bn_m    = (const float*)d_in[10];
    const float* bn_v    = (const float*)d_in[11];
    const float* pW1     = (const float*)d_in[12];
    const float* pb1     = (const float*)d_in[13];
    const float* pW2     = (const float*)d_in[14];
    const float* pb2     = (const float*)d_in[15];
    const float* bilW    = (const float*)d_in[16];
    const float* bilb    = (const float*)d_in[17];
    const float* cW1     = (const float*)d_in[18];
    const float* cb1     = (const float*)d_in[19];
    const float* cW2     = (const float*)d_in[20];
    const float* cb2     = (const float*)d_in[21];
    float* out = (float*)d_out;

    __half* h16 = nullptr; __half* u16 = nullptr; __half* w16 = nullptr;
    cudaGetSymbolAddress((void**)&h16, g_h16);
    cudaGetSymbolAddress((void**)&u16, g_u16);
    cudaGetSymbolAddress((void**)&w16, g_W16);

    const int TB = 256;
    int prep_blocks = (NN + TB - 1) / TB + 1;    // last block = pocket MLP
    k_prep<<<prep_blocks, TB>>>(x, convs_W, ei, pocket, pW1, pb1, pW2, pb2, bilW);
    k_deg_count<<<(NE / 4 + TB - 1) / TB, TB>>>(ei);
    k_scan<<<NB, 1024>>>();
    k_scatter<<<(NE / 4 + TB - 1) / TB, TB>>>(ei);

    int agg_blocks = (NN * 32 + TB - 1) / TB;

    // layer 0: fused 7-dim agg + GEMM + BN + ReLU
    k_layer0<<<(NN + 127) / 128, 128>>>(conv0_W, conv0_b, bn_g, bn_b, bn_m, bn_v);
    // layers 1,2: aggregate then tensor-core GEMM
    for (int l = 1; l <= 2; l++) {
        const __half* Wl = w16 + (long long)(l - 1) * HH * HH;
        const float* b = convs_b + (l - 1) * HH;
        k_agg<<<agg_blocks, TB>>>(h16, u16);
        k_gemm_tc<<<NP / 64, 128>>>(u16, Wl, h16, b,
                                    bn_g + l * HH, bn_b + l * HH,
                                    bn_m + l * HH, bn_v + l * HH);
    }

    // pool + bilinear + classifier
    k_pool_final<<<GG, 64>>>(batch, bilb, cW1, cb1, cW2, cb2, out);
}